// round 6
// baseline (speedup 1.0000x reference)
#include <cuda_runtime.h>
#include <cuda_fp16.h>
#include <cstdint>

// Problem constants (AGTLayer: N=32768, D=512, H=8, HD=64)
#define NROWS 32768
#define DDIM  512
#define NHEADS 8
#define HDIM  64
#define LN_EPS 1e-5f

// ---------------------------------------------------------------------------
// Scratch (__device__ globals; allocation-free rule)
// ---------------------------------------------------------------------------
__device__ __half g_h_hi[(size_t)NROWS * DDIM];
__device__ __half g_h_lo[(size_t)NROWS * DDIM];
__device__ __half g_at_hi[(size_t)NROWS * DDIM];
__device__ __half g_at_lo[(size_t)NROWS * DDIM];
__device__ __half g_wt_hi[4 * DDIM * DDIM];   // transposed: Wt[n][k]
__device__ __half g_wt_lo[4 * DDIM * DDIM];
__device__ float g_fh[(size_t)NROWS * DDIM];

// ---------------------------------------------------------------------------
// helpers
// ---------------------------------------------------------------------------
__device__ __forceinline__ uint32_t s2u(const void* p) {
    uint32_t a;
    asm("{ .reg .u64 t; cvta.to.shared.u64 t, %1; cvt.u32.u64 %0, t; }"
        : "=r"(a) : "l"(p));
    return a;
}

__device__ __forceinline__ void cpasync16(uint32_t dst, const void* src) {
    asm volatile("cp.async.cg.shared.global [%0], [%1], 16;" :: "r"(dst), "l"(src));
}
__device__ __forceinline__ void cp_commit() {
    asm volatile("cp.async.commit_group;" ::: "memory");
}
__device__ __forceinline__ void cp_wait2() {
    asm volatile("cp.async.wait_group 2;" ::: "memory");
}

__device__ __forceinline__ void ldm_x4(uint32_t* r, uint32_t addr) {
    asm volatile("ldmatrix.sync.aligned.m8n8.x4.shared.b16 {%0,%1,%2,%3}, [%4];"
                 : "=r"(r[0]), "=r"(r[1]), "=r"(r[2]), "=r"(r[3]) : "r"(addr));
}

__device__ __forceinline__ void mma16816(float* c, const uint32_t* a, const uint32_t* b) {
    asm volatile(
        "mma.sync.aligned.m16n8k16.row.col.f32.f16.f16.f32 "
        "{%0,%1,%2,%3}, {%4,%5,%6,%7}, {%8,%9}, {%0,%1,%2,%3};"
        : "+f"(c[0]), "+f"(c[1]), "+f"(c[2]), "+f"(c[3])
        : "r"(a[0]), "r"(a[1]), "r"(a[2]), "r"(a[3]), "r"(b[0]), "r"(b[1]));
}

// ---------------------------------------------------------------------------
// Conversion: fp32 -> fp16 hi/lo (element-wise, vectorized)
// ---------------------------------------------------------------------------
__global__ __launch_bounds__(256) void conv_h(const float* __restrict__ src,
                                              __half* __restrict__ hi,
                                              __half* __restrict__ lo) {
    const size_t i4 = (size_t)blockIdx.x * 256 + threadIdx.x;
    float4 x = ((const float4*)src)[i4];
    float f[4] = {x.x, x.y, x.z, x.w};
    __half H[4], L[4];
#pragma unroll
    for (int i = 0; i < 4; ++i) {
        H[i] = __float2half(f[i]);
        L[i] = __float2half(f[i] - __half2float(H[i]));
    }
    __half2 h01, h23, l01, l23;
    h01.x = H[0]; h01.y = H[1]; h23.x = H[2]; h23.y = H[3];
    l01.x = L[0]; l01.y = L[1]; l23.x = L[2]; l23.y = L[3];
    ((__half2*)hi)[i4 * 2]     = h01;
    ((__half2*)hi)[i4 * 2 + 1] = h23;
    ((__half2*)lo)[i4 * 2]     = l01;
    ((__half2*)lo)[i4 * 2 + 1] = l23;
}

// ---------------------------------------------------------------------------
// Conversion + transpose: W[k][n] fp32 -> Wt[n][k] fp16 hi/lo (4 matrices)
// ---------------------------------------------------------------------------
__global__ __launch_bounds__(256) void conv_wt(const float* __restrict__ W0,
                                               const float* __restrict__ W1,
                                               const float* __restrict__ W2,
                                               const float* __restrict__ W3,
                                               __half* __restrict__ hi,
                                               __half* __restrict__ lo) {
    const float* W = (blockIdx.z == 0) ? W0 : (blockIdx.z == 1) ? W1
                     : (blockIdx.z == 2) ? W2 : W3;
    __shared__ float t[32][33];
    const int tx = threadIdx.x, ty = threadIdx.y;  // 32 x 8
    const int n0 = blockIdx.x * 32, k0 = blockIdx.y * 32;
#pragma unroll
    for (int i = 0; i < 4; ++i)
        t[ty + i * 8][tx] = W[(size_t)(k0 + ty + i * 8) * DDIM + n0 + tx];
    __syncthreads();
    const size_t base = (size_t)blockIdx.z * DDIM * DDIM;
#pragma unroll
    for (int i = 0; i < 4; ++i) {
        const int n = n0 + ty + i * 8;
        const int k = k0 + tx;
        const float v = t[tx][ty + i * 8];
        const __half hv = __float2half(v);
        hi[base + (size_t)n * DDIM + k] = hv;
        lo[base + (size_t)n * DDIM + k] = __float2half(v - __half2float(hv));
    }
}

// ---------------------------------------------------------------------------
// HMMA split-fp16 GEMM: C[M,512] fp32 = A @ Wt^T  (3-term: AhBh + AhBl + AlBh)
// CTA 128x128, BK=32, 8 warps (warp tile 64x32), 4-stage cp.async pipeline,
// ldmatrix fragment loads. QKV=true: gridDim.z=3 selects weight slab + output
// slab (contiguous q,k,v) and relu for z<2.
// ---------------------------------------------------------------------------
#define ASTRIDE_B 80                      // bytes per padded smem row (40 halves)
#define TILE_B    (128 * ASTRIDE_B)      // 10240 B per operand tile
#define STAGE_B   (4 * TILE_B)           // Ah, Al, Bh, Bl = 40960 B
#define NSTAGE    4
#define SMEM_DYN  (NSTAGE * STAGE_B)     // 163840 B

template <bool QKV, bool RELU0>
__global__ __launch_bounds__(256) void gemm_mma(const __half* __restrict__ Ah,
                                                const __half* __restrict__ Al,
                                                const __half* __restrict__ Bh0,
                                                const __half* __restrict__ Bl0,
                                                float* __restrict__ C0) {
    extern __shared__ char dsm[];
    const uint32_t sb = s2u(dsm);

    const int tid  = threadIdx.x;
    const int wid  = tid >> 5;
    const int lane = tid & 31;
    const int bm   = blockIdx.y * 128;
    const int bn   = blockIdx.x * 128;

    const size_t zoffW = QKV ? (size_t)blockIdx.z * DDIM * DDIM : 0;
    const size_t zoffC = QKV ? (size_t)blockIdx.z * NROWS * DDIM : 0;
    const __half* Bh = Bh0 + zoffW;
    const __half* Bl = Bl0 + zoffW;
    float* C = C0 + zoffC;
    const bool relu = QKV ? (blockIdx.z < 2) : RELU0;

    const int wm = (wid & 1) * 64;   // warp m offset
    const int wn = (wid >> 1) * 32;  // warp n offset

    float acc[4][4][4];
#pragma unroll
    for (int i = 0; i < 4; ++i)
#pragma unroll
        for (int j = 0; j < 4; ++j)
#pragma unroll
            for (int r = 0; r < 4; ++r) acc[i][j][r] = 0.0f;

    // stage loader: 4 operand tiles, 2048 16B-chunks/stage, 8 per thread
    auto load_stage = [&](int stage, int kc) {
        const uint32_t s0 = sb + stage * STAGE_B;
        const __half* srcs[4] = {Ah, Al, Bh, Bl};
        const int rows[4] = {bm, bm, bn, bn};
#pragma unroll
        for (int tile = 0; tile < 4; ++tile) {
#pragma unroll
            for (int it = 0; it < 2; ++it) {
                const int ch  = tid + it * 256;     // 0..511
                const int row = ch >> 2;
                const int off = ch & 3;
                cpasync16(s0 + tile * TILE_B + row * ASTRIDE_B + off * 16,
                          srcs[tile] + (size_t)(rows[tile] + row) * DDIM + kc + off * 8);
            }
        }
    };

    // prologue: stages 0..2
#pragma unroll
    for (int s = 0; s < 3; ++s) {
        load_stage(s, s * 32);
        cp_commit();
    }

    // ldmatrix lane addressing (within a tile)
    const int a_row = (lane & 15);          // + wm + i*16
    const int a_co  = (lane >> 4) * 16;     // k-half byte offset
    const int b_row = ((lane >> 4) & 1) * 8 + (lane & 7);  // + wn + jp*16
    const int b_co  = ((lane >> 3) & 1) * 16;

    for (int kt = 0; kt < 16; ++kt) {
        cp_wait2();          // stage kt resident
        __syncthreads();     // visibility of all threads' chunks + stage kt-1 free

        if (kt + 3 < 16) load_stage((kt + 3) & (NSTAGE - 1), (kt + 3) * 32);
        cp_commit();

        const uint32_t s0   = sb + (kt & (NSTAGE - 1)) * STAGE_B;
        const uint32_t aho  = s0;
        const uint32_t alo_ = s0 + TILE_B;
        const uint32_t bho  = s0 + 2 * TILE_B;
        const uint32_t blo  = s0 + 3 * TILE_B;

#pragma unroll
        for (int s = 0; s < 2; ++s) {
            const int kb = s * 16;           // k offset (halves) in stage
            // B fragments: 2x ldmatrix.x4 per operand cover j=0..3
            uint32_t bh[4][2], bl[4][2];
#pragma unroll
            for (int jp = 0; jp < 2; ++jp) {
                const uint32_t ba =
                    (uint32_t)((wn + jp * 16 + b_row) * ASTRIDE_B + kb * 2 + b_co);
                uint32_t r[4];
                ldm_x4(r, bho + ba);
                bh[jp * 2][0] = r[0]; bh[jp * 2][1] = r[1];
                bh[jp * 2 + 1][0] = r[2]; bh[jp * 2 + 1][1] = r[3];
                ldm_x4(r, blo + ba);
                bl[jp * 2][0] = r[0]; bl[jp * 2][1] = r[1];
                bl[jp * 2 + 1][0] = r[2]; bl[jp * 2 + 1][1] = r[3];
            }
#pragma unroll
            for (int i = 0; i < 4; ++i) {
                const uint32_t aa =
                    (uint32_t)((wm + i * 16 + a_row) * ASTRIDE_B + kb * 2 + a_co);
                uint32_t ah[4], al[4];
                ldm_x4(ah, aho + aa);
                ldm_x4(al, alo_ + aa);
#pragma unroll
                for (int j = 0; j < 4; ++j) {
                    mma16816(acc[i][j], ah, bh[j]);
                    mma16816(acc[i][j], ah, bl[j]);
                    mma16816(acc[i][j], al, bh[j]);
                }
            }
        }
    }

    __syncthreads();

    // epilogue: acc -> padded smem -> coalesced fp32 stores
    const int r4 = lane >> 2;
    const int c2 = (lane & 3) * 2;
    float* Csh = (float*)dsm;   // 128 x 132
#pragma unroll
    for (int i = 0; i < 4; ++i) {
#pragma unroll
        for (int j = 0; j < 4; ++j) {
            const int row = wm + i * 16 + r4;
            const int col = wn + j * 8 + c2;
            float d0 = acc[i][j][0], d1 = acc[i][j][1];
            float d2 = acc[i][j][2], d3 = acc[i][j][3];
            if (relu) {
                d0 = fmaxf(d0, 0.0f); d1 = fmaxf(d1, 0.0f);
                d2 = fmaxf(d2, 0.0f); d3 = fmaxf(d3, 0.0f);
            }
            *(float2*)&Csh[row * 132 + col]       = make_float2(d0, d1);
            *(float2*)&Csh[(row + 8) * 132 + col] = make_float2(d2, d3);
        }
    }
    __syncthreads();

#pragma unroll
    for (int i = 0; i < 16; ++i) {
        const int idx = tid + i * 256;   // float4 id, 0..4095
        const int r   = idx >> 5;
        const int c4  = (idx & 31) * 4;
        const float* cr = Csh + r * 132 + c4;
        *(float4*)(C + (size_t)(bm + r) * DDIM + bn + c4) =
            make_float4(cr[0], cr[1], cr[2], cr[3]);
    }
}

// ---------------------------------------------------------------------------
// Per-node linear attention via 8x8 score matrix; emits fp16 hi/lo for Wf GEMM.
// ---------------------------------------------------------------------------
#define PADR 68

__global__ __launch_bounds__(256) void attn2(const float* __restrict__ q,
                                             const float* __restrict__ k,
                                             const float* __restrict__ v,
                                             __half* __restrict__ ahi,
                                             __half* __restrict__ alo) {
    __shared__ float sq[4][NHEADS * PADR];
    __shared__ float sk[4][NHEADS * PADR];
    __shared__ float sv[4][NHEADS * PADR];
    __shared__ float Ss[4][NHEADS * NHEADS];

    const int tid = threadIdx.x;
    const int ln  = tid >> 6;
    const int t   = tid & 63;
    const size_t base = ((size_t)blockIdx.x * 4 + ln) * DDIM;

#pragma unroll
    for (int c = 0; c < 2; ++c) {
        const int i = t * 4 + c * 256;
        const int h = i >> 6;
        const int d = i & 63;
        *(float4*)&sq[ln][h * PADR + d] = *(const float4*)(q + base + i);
        *(float4*)&sk[ln][h * PADR + d] = *(const float4*)(k + base + i);
        *(float4*)&sv[ln][h * PADR + d] = *(const float4*)(v + base + i);
    }
    __syncthreads();

    {
        const float* qp = &sq[ln][(t >> 3) * PADR];
        const float* kp = &sk[ln][(t & 7) * PADR];
        float s = 0.0f;
#pragma unroll
        for (int d = 0; d < HDIM; ++d) s = fmaf(qp[d], kp[d], s);
        Ss[ln][t] = s;
    }
    __syncthreads();

    {
        const int e = t;
#pragma unroll
        for (int h = 0; h < NHEADS; ++h) {
            float num = 0.0f, den = 0.0f;
#pragma unroll
            for (int hp = 0; hp < NHEADS; ++hp) {
                const float Sv = Ss[ln][h * NHEADS + hp];
                den += Sv;
                num = fmaf(Sv, sv[ln][hp * PADR + e], num);
            }
            const float a = num / den;
            const __half hv = __float2half(a);
            ahi[base + h * HDIM + e] = hv;
            alo[base + h * HDIM + e] = __float2half(a - __half2float(hv));
        }
    }
}

// ---------------------------------------------------------------------------
// Fused residual + LayerNorm, one warp per row.
// ---------------------------------------------------------------------------
__global__ __launch_bounds__(256) void ln_kernel(const float* __restrict__ h,
                                                 const float* __restrict__ fh,
                                                 const float* __restrict__ gamma,
                                                 const float* __restrict__ beta,
                                                 float* __restrict__ out) {
    const int row  = (blockIdx.x * blockDim.x + threadIdx.x) >> 5;
    const int lane = threadIdx.x & 31;
    if (row >= NROWS) return;

    const size_t base = (size_t)row * DDIM;
    float x[16];
    float s = 0.0f;
#pragma unroll
    for (int i = 0; i < 16; ++i) {
        const int c = lane + i * 32;
        x[i] = h[base + c] + fh[base + c];
        s += x[i];
    }
#pragma unroll
    for (int off = 16; off > 0; off >>= 1) s += __shfl_xor_sync(0xffffffffu, s, off);
    const float mu = s * (1.0f / DDIM);

    float var = 0.0f;
#pragma unroll
    for (int i = 0; i < 16; ++i) {
        const float d = x[i] - mu;
        var = fmaf(d, d, var);
    }
#pragma unroll
    for (int off = 16; off > 0; off >>= 1) var += __shfl_xor_sync(0xffffffffu, var, off);
    var *= (1.0f / DDIM);

    const float r = rsqrtf(var + LN_EPS);
#pragma unroll
    for (int i = 0; i < 16; ++i) {
        const int c = lane + i * 32;
        out[base + c] = (x[i] - mu) * r * gamma[c] + beta[c];
    }
}

// ---------------------------------------------------------------------------
// kernel_launch
// ---------------------------------------------------------------------------
extern "C" void kernel_launch(void* const* d_in, const int* in_sizes, int n_in,
                              void* d_out, int out_size) {
    const float* h     = (const float*)d_in[0];
    const float* Wq    = (const float*)d_in[1];
    const float* Wk    = (const float*)d_in[2];
    const float* Wv    = (const float*)d_in[3];
    const float* Wf    = (const float*)d_in[4];
    const float* gamma = (const float*)d_in[5];
    const float* beta  = (const float*)d_in[6];

    float* out = (float*)d_out;
    float* q   = out + (size_t)NROWS * DDIM;
    float* k   = out + 2 * (size_t)NROWS * DDIM;
    float* v   = out + 3 * (size_t)NROWS * DDIM;

    void *hhi, *hlo, *athi, *atlo, *wthi, *wtlo, *fhp;
    cudaGetSymbolAddress(&hhi, g_h_hi);
    cudaGetSymbolAddress(&hlo, g_h_lo);
    cudaGetSymbolAddress(&athi, g_at_hi);
    cudaGetSymbolAddress(&atlo, g_at_lo);
    cudaGetSymbolAddress(&wthi, g_wt_hi);
    cudaGetSymbolAddress(&wtlo, g_wt_lo);
    cudaGetSymbolAddress(&fhp, g_fh);

    cudaFuncSetAttribute(gemm_mma<true, false>,
                         cudaFuncAttributeMaxDynamicSharedMemorySize, SMEM_DYN);
    cudaFuncSetAttribute(gemm_mma<false, false>,
                         cudaFuncAttributeMaxDynamicSharedMemorySize, SMEM_DYN);

    __half* Hhi = (__half*)hhi;
    __half* Hlo = (__half*)hlo;
    __half* WTh = (__half*)wthi;
    __half* WTl = (__half*)wtlo;

    conv_h<<<(NROWS * DDIM) / 4 / 256, 256>>>(h, Hhi, Hlo);
    conv_wt<<<dim3(16, 16, 4), dim3(32, 8)>>>(Wq, Wk, Wv, Wf, WTh, WTl);

    const size_t WSZ = (size_t)DDIM * DDIM;

    // fused q,k,v projections (z = 0,1,2); outputs are contiguous slabs
    gemm_mma<true, false><<<dim3(4, 256, 3), 256, SMEM_DYN>>>(Hhi, Hlo, WTh, WTl, q);

    attn2<<<NROWS / 4, 256>>>(q, k, v, (__half*)athi, (__half*)atlo);

    gemm_mma<false, false><<<dim3(4, 256, 1), 256, SMEM_DYN>>>(
        (__half*)athi, (__half*)atlo, WTh + 3 * WSZ, WTl + 3 * WSZ, (float*)fhp);

    ln_kernel<<<(NROWS * 32) / 256, 256>>>(h, (const float*)fhp, gamma, beta, out);
}

// round 7
// speedup vs baseline: 1.2608x; 1.2608x over previous
#include <cuda_runtime.h>
#include <cuda_fp16.h>
#include <cstdint>

// Problem constants (AGTLayer: N=32768, D=512, H=8, HD=64)
#define NROWS 32768
#define DDIM  512
#define NHEADS 8
#define HDIM  64
#define LN_EPS 1e-5f

// ---------------------------------------------------------------------------
// Scratch (__device__ globals; allocation-free rule)
// ---------------------------------------------------------------------------
__device__ __half g_h_hi[(size_t)NROWS * DDIM];
__device__ __half g_h_lo[(size_t)NROWS * DDIM];
__device__ __half g_at_hi[(size_t)NROWS * DDIM];
__device__ __half g_at_lo[(size_t)NROWS * DDIM];
__device__ __half g_wt_hi[4 * DDIM * DDIM];   // transposed: Wt[n][k]
__device__ __half g_wt_lo[4 * DDIM * DDIM];
__device__ float g_fh[(size_t)NROWS * DDIM];

// ---------------------------------------------------------------------------
// helpers
// ---------------------------------------------------------------------------
__device__ __forceinline__ uint32_t s2u(const void* p) {
    uint32_t a;
    asm("{ .reg .u64 t; cvta.to.shared.u64 t, %1; cvt.u32.u64 %0, t; }"
        : "=r"(a) : "l"(p));
    return a;
}

__device__ __forceinline__ void cpasync16(uint32_t dst, const void* src) {
    asm volatile("cp.async.cg.shared.global [%0], [%1], 16;" :: "r"(dst), "l"(src));
}
__device__ __forceinline__ void cp_commit() {
    asm volatile("cp.async.commit_group;" ::: "memory");
}
__device__ __forceinline__ void cp_wait1() {
    asm volatile("cp.async.wait_group 1;" ::: "memory");
}

__device__ __forceinline__ void ldm_x4(uint32_t* r, uint32_t addr) {
    asm volatile("ldmatrix.sync.aligned.m8n8.x4.shared.b16 {%0,%1,%2,%3}, [%4];"
                 : "=r"(r[0]), "=r"(r[1]), "=r"(r[2]), "=r"(r[3]) : "r"(addr));
}

__device__ __forceinline__ void mma16816(float* c, const uint32_t* a, const uint32_t* b) {
    asm volatile(
        "mma.sync.aligned.m16n8k16.row.col.f32.f16.f16.f32 "
        "{%0,%1,%2,%3}, {%4,%5,%6,%7}, {%8,%9}, {%0,%1,%2,%3};"
        : "+f"(c[0]), "+f"(c[1]), "+f"(c[2]), "+f"(c[3])
        : "r"(a[0]), "r"(a[1]), "r"(a[2]), "r"(a[3]), "r"(b[0]), "r"(b[1]));
}

// swizzled smem byte offset within a tile: rows of 64 B (32 halves), 4 16B segs
__device__ __forceinline__ uint32_t swz(int row, int seg) {
    return (uint32_t)(row * 64 + ((seg ^ ((row >> 1) & 3)) << 4));
}

// ---------------------------------------------------------------------------
// Conversion: fp32 -> fp16 hi/lo (element-wise, vectorized)
// ---------------------------------------------------------------------------
__global__ __launch_bounds__(256) void conv_h(const float* __restrict__ src,
                                              __half* __restrict__ hi,
                                              __half* __restrict__ lo) {
    const size_t i4 = (size_t)blockIdx.x * 256 + threadIdx.x;
    float4 x = ((const float4*)src)[i4];
    float f[4] = {x.x, x.y, x.z, x.w};
    __half H[4], L[4];
#pragma unroll
    for (int i = 0; i < 4; ++i) {
        H[i] = __float2half(f[i]);
        L[i] = __float2half(f[i] - __half2float(H[i]));
    }
    __half2 h01, h23, l01, l23;
    h01.x = H[0]; h01.y = H[1]; h23.x = H[2]; h23.y = H[3];
    l01.x = L[0]; l01.y = L[1]; l23.x = L[2]; l23.y = L[3];
    ((__half2*)hi)[i4 * 2]     = h01;
    ((__half2*)hi)[i4 * 2 + 1] = h23;
    ((__half2*)lo)[i4 * 2]     = l01;
    ((__half2*)lo)[i4 * 2 + 1] = l23;
}

// ---------------------------------------------------------------------------
// Conversion + transpose: W[k][n] fp32 -> Wt[n][k] fp16 hi/lo (4 matrices)
// ---------------------------------------------------------------------------
__global__ __launch_bounds__(256) void conv_wt(const float* __restrict__ W0,
                                               const float* __restrict__ W1,
                                               const float* __restrict__ W2,
                                               const float* __restrict__ W3,
                                               __half* __restrict__ hi,
                                               __half* __restrict__ lo) {
    const float* W = (blockIdx.z == 0) ? W0 : (blockIdx.z == 1) ? W1
                     : (blockIdx.z == 2) ? W2 : W3;
    __shared__ float t[32][33];
    const int tx = threadIdx.x, ty = threadIdx.y;  // 32 x 8
    const int n0 = blockIdx.x * 32, k0 = blockIdx.y * 32;
#pragma unroll
    for (int i = 0; i < 4; ++i)
        t[ty + i * 8][tx] = W[(size_t)(k0 + ty + i * 8) * DDIM + n0 + tx];
    __syncthreads();
    const size_t base = (size_t)blockIdx.z * DDIM * DDIM;
#pragma unroll
    for (int i = 0; i < 4; ++i) {
        const int n = n0 + ty + i * 8;
        const int k = k0 + tx;
        const float v = t[tx][ty + i * 8];
        const __half hv = __float2half(v);
        hi[base + (size_t)n * DDIM + k] = hv;
        lo[base + (size_t)n * DDIM + k] = __float2half(v - __half2float(hv));
    }
}

// ---------------------------------------------------------------------------
// HMMA split-fp16 GEMM: C[M,512] fp32 = A @ Wt^T  (3-term: AhBh + AhBl + AlBh)
// CTA 128x128, BK=32, 8 warps (warp tile 64x32), 3-stage cp.async pipeline,
// swizzled 64B-row smem tiles + ldmatrix. 96KB smem -> 2 CTAs/SM.
// QKV=true: gridDim.z selects weight/output slab; relu for z<2.
// ---------------------------------------------------------------------------
#define TILE_B    (128 * 64)             // 8192 B per operand tile
#define STAGE_B   (4 * TILE_B)           // Ah, Al, Bh, Bl = 32768 B
#define NSTAGE    3
#define SMEM_DYN  (NSTAGE * STAGE_B)     // 98304 B (epilogue 128*132*4=67584 fits)

template <bool QKV, bool RELU0>
__global__ __launch_bounds__(256) void gemm_mma(const __half* __restrict__ Ah,
                                                const __half* __restrict__ Al,
                                                const __half* __restrict__ Bh0,
                                                const __half* __restrict__ Bl0,
                                                float* __restrict__ C0) {
    extern __shared__ char dsm[];
    const uint32_t sb = s2u(dsm);

    const int tid  = threadIdx.x;
    const int wid  = tid >> 5;
    const int lane = tid & 31;
    const int bm   = blockIdx.y * 128;
    const int bn   = blockIdx.x * 128;

    const size_t zoffW = QKV ? (size_t)blockIdx.z * DDIM * DDIM : 0;
    const size_t zoffC = QKV ? (size_t)blockIdx.z * NROWS * DDIM : 0;
    const __half* Bh = Bh0 + zoffW;
    const __half* Bl = Bl0 + zoffW;
    float* C = C0 + zoffC;
    const bool relu = QKV ? (blockIdx.z < 2) : RELU0;

    const int wm = (wid & 1) * 64;   // warp m offset
    const int wn = (wid >> 1) * 32;  // warp n offset

    float acc[4][4][4];
#pragma unroll
    for (int i = 0; i < 4; ++i)
#pragma unroll
        for (int j = 0; j < 4; ++j)
#pragma unroll
            for (int r = 0; r < 4; ++r) acc[i][j][r] = 0.0f;

    // stage loader: 4 operand tiles, 512 16B-chunks per tile, 2 per thread/tile
    auto load_stage = [&](int stage, int kc) {
        const uint32_t s0 = sb + stage * STAGE_B;
        const __half* srcs[4] = {Ah, Al, Bh, Bl};
        const int rows[4] = {bm, bm, bn, bn};
#pragma unroll
        for (int tile = 0; tile < 4; ++tile) {
#pragma unroll
            for (int it = 0; it < 2; ++it) {
                const int ch  = tid + it * 256;     // 0..511
                const int row = ch >> 2;
                const int seg = ch & 3;
                cpasync16(s0 + tile * TILE_B + swz(row, seg),
                          srcs[tile] + (size_t)(rows[tile] + row) * DDIM + kc + seg * 8);
            }
        }
    };

    // prologue: stages 0,1
    load_stage(0, 0);
    cp_commit();
    load_stage(1, 32);
    cp_commit();

    // ldmatrix lane roles
    const int a_row = lane & 15;                 // + wm + i*16
    const int a_sg  = lane >> 4;                 // k-half 16B seg (0/1 within k16)
    const int b_row = ((lane >> 4) & 1) * 8 + (lane & 7);  // + wn + jp*16
    const int b_sg  = (lane >> 3) & 1;

    for (int kt = 0; kt < 16; ++kt) {
        cp_wait1();          // stage kt resident (all but newest group done)
        __syncthreads();     // + all threads done computing stage (kt+2)%3

        if (kt + 2 < 16) load_stage((kt + 2) % NSTAGE, (kt + 2) * 32);
        cp_commit();

        const uint32_t s0   = sb + (kt % NSTAGE) * STAGE_B;
        const uint32_t aho  = s0;
        const uint32_t alo_ = s0 + TILE_B;
        const uint32_t bho  = s0 + 2 * TILE_B;
        const uint32_t blo  = s0 + 3 * TILE_B;

#pragma unroll
        for (int s = 0; s < 2; ++s) {
            const int ksg = s * 2;               // 16B-seg base of this k16
            uint32_t bh[4][2], bl[4][2];
#pragma unroll
            for (int jp = 0; jp < 2; ++jp) {
                const uint32_t ba = swz(wn + jp * 16 + b_row, ksg + b_sg);
                uint32_t r[4];
                ldm_x4(r, bho + ba);
                bh[jp * 2][0] = r[0]; bh[jp * 2][1] = r[1];
                bh[jp * 2 + 1][0] = r[2]; bh[jp * 2 + 1][1] = r[3];
                ldm_x4(r, blo + ba);
                bl[jp * 2][0] = r[0]; bl[jp * 2][1] = r[1];
                bl[jp * 2 + 1][0] = r[2]; bl[jp * 2 + 1][1] = r[3];
            }
#pragma unroll
            for (int i = 0; i < 4; ++i) {
                const uint32_t aa = swz(wm + i * 16 + a_row, ksg + a_sg);
                uint32_t ah[4], al[4];
                ldm_x4(ah, aho + aa);
                ldm_x4(al, alo_ + aa);
#pragma unroll
                for (int j = 0; j < 4; ++j) {
                    mma16816(acc[i][j], ah, bh[j]);
                    mma16816(acc[i][j], ah, bl[j]);
                    mma16816(acc[i][j], al, bh[j]);
                }
            }
        }
    }

    __syncthreads();

    // epilogue: acc -> padded smem -> coalesced fp32 stores
    const int r4 = lane >> 2;
    const int c2 = (lane & 3) * 2;
    float* Csh = (float*)dsm;   // 128 x 132
#pragma unroll
    for (int i = 0; i < 4; ++i) {
#pragma unroll
        for (int j = 0; j < 4; ++j) {
            const int row = wm + i * 16 + r4;
            const int col = wn + j * 8 + c2;
            float d0 = acc[i][j][0], d1 = acc[i][j][1];
            float d2 = acc[i][j][2], d3 = acc[i][j][3];
            if (relu) {
                d0 = fmaxf(d0, 0.0f); d1 = fmaxf(d1, 0.0f);
                d2 = fmaxf(d2, 0.0f); d3 = fmaxf(d3, 0.0f);
            }
            *(float2*)&Csh[row * 132 + col]       = make_float2(d0, d1);
            *(float2*)&Csh[(row + 8) * 132 + col] = make_float2(d2, d3);
        }
    }
    __syncthreads();

#pragma unroll
    for (int i = 0; i < 16; ++i) {
        const int idx = tid + i * 256;   // float4 id, 0..4095
        const int r   = idx >> 5;
        const int c4  = (idx & 31) * 4;
        const float* cr = Csh + r * 132 + c4;
        *(float4*)(C + (size_t)(bm + r) * DDIM + bn + c4) =
            make_float4(cr[0], cr[1], cr[2], cr[3]);
    }
}

// ---------------------------------------------------------------------------
// Per-node linear attention via 8x8 score matrix; emits fp16 hi/lo for Wf GEMM.
// ---------------------------------------------------------------------------
#define PADR 68

__global__ __launch_bounds__(256) void attn2(const float* __restrict__ q,
                                             const float* __restrict__ k,
                                             const float* __restrict__ v,
                                             __half* __restrict__ ahi,
                                             __half* __restrict__ alo) {
    __shared__ float sq[4][NHEADS * PADR];
    __shared__ float sk[4][NHEADS * PADR];
    __shared__ float sv[4][NHEADS * PADR];
    __shared__ float Ss[4][NHEADS * NHEADS];

    const int tid = threadIdx.x;
    const int ln  = tid >> 6;
    const int t   = tid & 63;
    const size_t base = ((size_t)blockIdx.x * 4 + ln) * DDIM;

#pragma unroll
    for (int c = 0; c < 2; ++c) {
        const int i = t * 4 + c * 256;
        const int h = i >> 6;
        const int d = i & 63;
        *(float4*)&sq[ln][h * PADR + d] = *(const float4*)(q + base + i);
        *(float4*)&sk[ln][h * PADR + d] = *(const float4*)(k + base + i);
        *(float4*)&sv[ln][h * PADR + d] = *(const float4*)(v + base + i);
    }
    __syncthreads();

    {
        const float* qp = &sq[ln][(t >> 3) * PADR];
        const float* kp = &sk[ln][(t & 7) * PADR];
        float s = 0.0f;
#pragma unroll
        for (int d = 0; d < HDIM; ++d) s = fmaf(qp[d], kp[d], s);
        Ss[ln][t] = s;
    }
    __syncthreads();

    {
        const int e = t;
#pragma unroll
        for (int h = 0; h < NHEADS; ++h) {
            float num = 0.0f, den = 0.0f;
#pragma unroll
            for (int hp = 0; hp < NHEADS; ++hp) {
                const float Sv = Ss[ln][h * NHEADS + hp];
                den += Sv;
                num = fmaf(Sv, sv[ln][hp * PADR + e], num);
            }
            const float a = num / den;
            const __half hv = __float2half(a);
            ahi[base + h * HDIM + e] = hv;
            alo[base + h * HDIM + e] = __float2half(a - __half2float(hv));
        }
    }
}

// ---------------------------------------------------------------------------
// Fused residual + LayerNorm, one warp per row.
// ---------------------------------------------------------------------------
__global__ __launch_bounds__(256) void ln_kernel(const float* __restrict__ h,
                                                 const float* __restrict__ fh,
                                                 const float* __restrict__ gamma,
                                                 const float* __restrict__ beta,
                                                 float* __restrict__ out) {
    const int row  = (blockIdx.x * blockDim.x + threadIdx.x) >> 5;
    const int lane = threadIdx.x & 31;
    if (row >= NROWS) return;

    const size_t base = (size_t)row * DDIM;
    float x[16];
    float s = 0.0f;
#pragma unroll
    for (int i = 0; i < 16; ++i) {
        const int c = lane + i * 32;
        x[i] = h[base + c] + fh[base + c];
        s += x[i];
    }
#pragma unroll
    for (int off = 16; off > 0; off >>= 1) s += __shfl_xor_sync(0xffffffffu, s, off);
    const float mu = s * (1.0f / DDIM);

    float var = 0.0f;
#pragma unroll
    for (int i = 0; i < 16; ++i) {
        const float d = x[i] - mu;
        var = fmaf(d, d, var);
    }
#pragma unroll
    for (int off = 16; off > 0; off >>= 1) var += __shfl_xor_sync(0xffffffffu, var, off);
    var *= (1.0f / DDIM);

    const float r = rsqrtf(var + LN_EPS);
#pragma unroll
    for (int i = 0; i < 16; ++i) {
        const int c = lane + i * 32;
        out[base + c] = (x[i] - mu) * r * gamma[c] + beta[c];
    }
}

// ---------------------------------------------------------------------------
// kernel_launch
// ---------------------------------------------------------------------------
extern "C" void kernel_launch(void* const* d_in, const int* in_sizes, int n_in,
                              void* d_out, int out_size) {
    const float* h     = (const float*)d_in[0];
    const float* Wq    = (const float*)d_in[1];
    const float* Wk    = (const float*)d_in[2];
    const float* Wv    = (const float*)d_in[3];
    const float* Wf    = (const float*)d_in[4];
    const float* gamma = (const float*)d_in[5];
    const float* beta  = (const float*)d_in[6];

    float* out = (float*)d_out;
    float* q   = out + (size_t)NROWS * DDIM;
    float* k   = out + 2 * (size_t)NROWS * DDIM;
    float* v   = out + 3 * (size_t)NROWS * DDIM;

    void *hhi, *hlo, *athi, *atlo, *wthi, *wtlo, *fhp;
    cudaGetSymbolAddress(&hhi, g_h_hi);
    cudaGetSymbolAddress(&hlo, g_h_lo);
    cudaGetSymbolAddress(&athi, g_at_hi);
    cudaGetSymbolAddress(&atlo, g_at_lo);
    cudaGetSymbolAddress(&wthi, g_wt_hi);
    cudaGetSymbolAddress(&wtlo, g_wt_lo);
    cudaGetSymbolAddress(&fhp, g_fh);

    cudaFuncSetAttribute(gemm_mma<true, false>,
                         cudaFuncAttributeMaxDynamicSharedMemorySize, SMEM_DYN);
    cudaFuncSetAttribute(gemm_mma<false, false>,
                         cudaFuncAttributeMaxDynamicSharedMemorySize, SMEM_DYN);

    __half* Hhi = (__half*)hhi;
    __half* Hlo = (__half*)hlo;
    __half* WTh = (__half*)wthi;
    __half* WTl = (__half*)wtlo;

    conv_h<<<(NROWS * DDIM) / 4 / 256, 256>>>(h, Hhi, Hlo);
    conv_wt<<<dim3(16, 16, 4), dim3(32, 8)>>>(Wq, Wk, Wv, Wf, WTh, WTl);

    const size_t WSZ = (size_t)DDIM * DDIM;

    // fused q,k,v projections (z = 0,1,2); outputs are contiguous slabs
    gemm_mma<true, false><<<dim3(4, 256, 3), 256, SMEM_DYN>>>(Hhi, Hlo, WTh, WTl, q);

    attn2<<<NROWS / 4, 256>>>(q, k, v, (__half*)athi, (__half*)atlo);

    gemm_mma<false, false><<<dim3(4, 256, 1), 256, SMEM_DYN>>>(
        (__half*)athi, (__half*)atlo, WTh + 3 * WSZ, WTl + 3 * WSZ, (float*)fhp);

    ln_kernel<<<(NROWS * 32) / 256, 256>>>(h, (const float*)fhp, gamma, beta, out);
}

// round 8
// speedup vs baseline: 1.3476x; 1.0689x over previous
#include <cuda_runtime.h>
#include <cuda_fp16.h>
#include <cstdint>

// Problem constants (AGTLayer: N=32768, D=512, H=8, HD=64)
#define NROWS 32768
#define DDIM  512
#define NHEADS 8
#define HDIM  64
#define LN_EPS 1e-5f

// ---------------------------------------------------------------------------
// Scratch (__device__ globals; allocation-free rule)
// ---------------------------------------------------------------------------
__device__ __half g_h_hi[(size_t)NROWS * DDIM];
__device__ __half g_h_lo[(size_t)NROWS * DDIM];
__device__ __half g_at_hi[(size_t)NROWS * DDIM];
__device__ __half g_wt_hi[4 * DDIM * DDIM];   // transposed: Wt[n][k]
__device__ __half g_wt_lo[4 * DDIM * DDIM];
__device__ float g_fh[(size_t)NROWS * DDIM];

// ---------------------------------------------------------------------------
// helpers
// ---------------------------------------------------------------------------
__device__ __forceinline__ uint32_t s2u(const void* p) {
    uint32_t a;
    asm("{ .reg .u64 t; cvta.to.shared.u64 t, %1; cvt.u32.u64 %0, t; }"
        : "=r"(a) : "l"(p));
    return a;
}

__device__ __forceinline__ void cpasync16(uint32_t dst, const void* src) {
    asm volatile("cp.async.cg.shared.global [%0], [%1], 16;" :: "r"(dst), "l"(src));
}
__device__ __forceinline__ void cp_commit() {
    asm volatile("cp.async.commit_group;" ::: "memory");
}
__device__ __forceinline__ void cp_wait1() {
    asm volatile("cp.async.wait_group 1;" ::: "memory");
}

__device__ __forceinline__ void ldm_x4(uint32_t* r, uint32_t addr) {
    asm volatile("ldmatrix.sync.aligned.m8n8.x4.shared.b16 {%0,%1,%2,%3}, [%4];"
                 : "=r"(r[0]), "=r"(r[1]), "=r"(r[2]), "=r"(r[3]) : "r"(addr));
}

__device__ __forceinline__ void mma16816(float* c, const uint32_t* a, const uint32_t* b) {
    asm volatile(
        "mma.sync.aligned.m16n8k16.row.col.f32.f16.f16.f32 "
        "{%0,%1,%2,%3}, {%4,%5,%6,%7}, {%8,%9}, {%0,%1,%2,%3};"
        : "+f"(c[0]), "+f"(c[1]), "+f"(c[2]), "+f"(c[3])
        : "r"(a[0]), "r"(a[1]), "r"(a[2]), "r"(a[3]), "r"(b[0]), "r"(b[1]));
}

// swizzled smem byte offset within a tile: rows of 64 B (32 halves), 4 16B segs
__device__ __forceinline__ uint32_t swz(int row, int seg) {
    return (uint32_t)(row * 64 + ((seg ^ ((row >> 1) & 3)) << 4));
}

// ---------------------------------------------------------------------------
// Conversion: fp32 -> fp16 hi/lo (element-wise, vectorized)
// ---------------------------------------------------------------------------
__global__ __launch_bounds__(256) void conv_h(const float* __restrict__ src,
                                              __half* __restrict__ hi,
                                              __half* __restrict__ lo) {
    const size_t i4 = (size_t)blockIdx.x * 256 + threadIdx.x;
    float4 x = ((const float4*)src)[i4];
    float f[4] = {x.x, x.y, x.z, x.w};
    __half H[4], L[4];
#pragma unroll
    for (int i = 0; i < 4; ++i) {
        H[i] = __float2half(f[i]);
        L[i] = __float2half(f[i] - __half2float(H[i]));
    }
    __half2 h01, h23, l01, l23;
    h01.x = H[0]; h01.y = H[1]; h23.x = H[2]; h23.y = H[3];
    l01.x = L[0]; l01.y = L[1]; l23.x = L[2]; l23.y = L[3];
    ((__half2*)hi)[i4 * 2]     = h01;
    ((__half2*)hi)[i4 * 2 + 1] = h23;
    ((__half2*)lo)[i4 * 2]     = l01;
    ((__half2*)lo)[i4 * 2 + 1] = l23;
}

// ---------------------------------------------------------------------------
// Conversion + transpose: W[k][n] fp32 -> Wt[n][k] fp16 hi/lo (4 matrices)
// ---------------------------------------------------------------------------
__global__ __launch_bounds__(256) void conv_wt(const float* __restrict__ W0,
                                               const float* __restrict__ W1,
                                               const float* __restrict__ W2,
                                               const float* __restrict__ W3,
                                               __half* __restrict__ hi,
                                               __half* __restrict__ lo) {
    const float* W = (blockIdx.z == 0) ? W0 : (blockIdx.z == 1) ? W1
                     : (blockIdx.z == 2) ? W2 : W3;
    __shared__ float t[32][33];
    const int tx = threadIdx.x, ty = threadIdx.y;  // 32 x 8
    const int n0 = blockIdx.x * 32, k0 = blockIdx.y * 32;
#pragma unroll
    for (int i = 0; i < 4; ++i)
        t[ty + i * 8][tx] = W[(size_t)(k0 + ty + i * 8) * DDIM + n0 + tx];
    __syncthreads();
    const size_t base = (size_t)blockIdx.z * DDIM * DDIM;
#pragma unroll
    for (int i = 0; i < 4; ++i) {
        const int n = n0 + ty + i * 8;
        const int k = k0 + tx;
        const float v = t[tx][ty + i * 8];
        const __half hv = __float2half(v);
        hi[base + (size_t)n * DDIM + k] = hv;
        lo[base + (size_t)n * DDIM + k] = __float2half(v - __half2float(hv));
    }
}

// ---------------------------------------------------------------------------
// HMMA split-fp16 GEMM: C[M,512] fp32 = A @ Wt^T
//   TERMS=3 (QKV): C = AhBh + AhBl + AlBh  (tiles Ah,Al,Bh,Bl)
//   TERMS=2 (Wf):  C = Ah(Bh + Bl)        (tiles Ah,Bh,Bl; A single fp16)
// CTA 128x128, BK=32, 8 warps (64x32), 3-stage cp.async, swizzled + ldmatrix.
// QKV=true: gridDim.z selects weight/output slab; relu for z<2.
// ---------------------------------------------------------------------------
#define TILE_B   (128 * 64)              // 8192 B per operand tile
#define NSTAGE   3

template <int TERMS, bool QKV>
__global__ __launch_bounds__(256) void gemm_mma(const __half* __restrict__ Ah,
                                                const __half* __restrict__ Al,
                                                const __half* __restrict__ Bh0,
                                                const __half* __restrict__ Bl0,
                                                float* __restrict__ C0) {
    constexpr int NTILES  = TERMS + 1;
    constexpr int STAGE_B = NTILES * TILE_B;

    extern __shared__ char dsm[];
    const uint32_t sb = s2u(dsm);

    const int tid  = threadIdx.x;
    const int wid  = tid >> 5;
    const int lane = tid & 31;
    const int bm   = blockIdx.y * 128;
    const int bn   = blockIdx.x * 128;

    const size_t zoffW = QKV ? (size_t)blockIdx.z * DDIM * DDIM : 0;
    const size_t zoffC = QKV ? (size_t)blockIdx.z * NROWS * DDIM : 0;
    const __half* Bh = Bh0 + zoffW;
    const __half* Bl = Bl0 + zoffW;
    float* C = C0 + zoffC;
    const bool relu = QKV ? (blockIdx.z < 2) : false;

    const int wm = (wid & 1) * 64;   // warp m offset
    const int wn = (wid >> 1) * 32;  // warp n offset

    float acc[4][4][4];
#pragma unroll
    for (int i = 0; i < 4; ++i)
#pragma unroll
        for (int j = 0; j < 4; ++j)
#pragma unroll
            for (int r = 0; r < 4; ++r) acc[i][j][r] = 0.0f;

    // stage loader
    const __half* srcs[4];
    int rws[4];
    srcs[0] = Ah; rws[0] = bm;
    if (TERMS == 3) {
        srcs[1] = Al; rws[1] = bm;
        srcs[2] = Bh; rws[2] = bn;
        srcs[3] = Bl; rws[3] = bn;
    } else {
        srcs[1] = Bh; rws[1] = bn;
        srcs[2] = Bl; rws[2] = bn;
        srcs[3] = Bl; rws[3] = bn;  // unused
    }

    auto load_stage = [&](int stage, int kc) {
        const uint32_t s0 = sb + stage * STAGE_B;
#pragma unroll
        for (int tile = 0; tile < NTILES; ++tile) {
#pragma unroll
            for (int it = 0; it < 2; ++it) {
                const int ch  = tid + it * 256;     // 0..511
                const int row = ch >> 2;
                const int seg = ch & 3;
                cpasync16(s0 + tile * TILE_B + swz(row, seg),
                          srcs[tile] + (size_t)(rws[tile] + row) * DDIM + kc + seg * 8);
            }
        }
    };

    // prologue: stages 0,1
    load_stage(0, 0);
    cp_commit();
    load_stage(1, 32);
    cp_commit();

    // ldmatrix lane roles
    const int a_row = lane & 15;
    const int a_sg  = lane >> 4;
    const int b_row = ((lane >> 4) & 1) * 8 + (lane & 7);
    const int b_sg  = (lane >> 3) & 1;

    for (int kt = 0; kt < 16; ++kt) {
        cp_wait1();
        __syncthreads();

        if (kt + 2 < 16) load_stage((kt + 2) % NSTAGE, (kt + 2) * 32);
        cp_commit();

        const uint32_t s0   = sb + (kt % NSTAGE) * STAGE_B;
        const uint32_t aho  = s0;
        const uint32_t alo_ = s0 + TILE_B;                       // TERMS==3 only
        const uint32_t bho  = s0 + (TERMS == 3 ? 2 : 1) * TILE_B;
        const uint32_t blo  = bho + TILE_B;

#pragma unroll
        for (int s = 0; s < 2; ++s) {
            const int ksg = s * 2;
            uint32_t bh[4][2], bl[4][2];
#pragma unroll
            for (int jp = 0; jp < 2; ++jp) {
                const uint32_t ba = swz(wn + jp * 16 + b_row, ksg + b_sg);
                uint32_t r[4];
                ldm_x4(r, bho + ba);
                bh[jp * 2][0] = r[0]; bh[jp * 2][1] = r[1];
                bh[jp * 2 + 1][0] = r[2]; bh[jp * 2 + 1][1] = r[3];
                ldm_x4(r, blo + ba);
                bl[jp * 2][0] = r[0]; bl[jp * 2][1] = r[1];
                bl[jp * 2 + 1][0] = r[2]; bl[jp * 2 + 1][1] = r[3];
            }
#pragma unroll
            for (int i = 0; i < 4; ++i) {
                const uint32_t aa = swz(wm + i * 16 + a_row, ksg + a_sg);
                uint32_t ah[4], al[4];
                ldm_x4(ah, aho + aa);
                if (TERMS == 3) ldm_x4(al, alo_ + aa);
#pragma unroll
                for (int j = 0; j < 4; ++j) {
                    mma16816(acc[i][j], ah, bh[j]);
                    mma16816(acc[i][j], ah, bl[j]);
                    if (TERMS == 3) mma16816(acc[i][j], al, bh[j]);
                }
            }
        }
    }

    __syncthreads();

    // epilogue: acc -> padded smem -> coalesced fp32 stores
    const int r4 = lane >> 2;
    const int c2 = (lane & 3) * 2;
    float* Csh = (float*)dsm;   // 128 x 132 floats = 67584 B
#pragma unroll
    for (int i = 0; i < 4; ++i) {
#pragma unroll
        for (int j = 0; j < 4; ++j) {
            const int row = wm + i * 16 + r4;
            const int col = wn + j * 8 + c2;
            float d0 = acc[i][j][0], d1 = acc[i][j][1];
            float d2 = acc[i][j][2], d3 = acc[i][j][3];
            if (relu) {
                d0 = fmaxf(d0, 0.0f); d1 = fmaxf(d1, 0.0f);
                d2 = fmaxf(d2, 0.0f); d3 = fmaxf(d3, 0.0f);
            }
            *(float2*)&Csh[row * 132 + col]       = make_float2(d0, d1);
            *(float2*)&Csh[(row + 8) * 132 + col] = make_float2(d2, d3);
        }
    }
    __syncthreads();

#pragma unroll
    for (int i = 0; i < 16; ++i) {
        const int idx = tid + i * 256;   // float4 id, 0..4095
        const int r   = idx >> 5;
        const int c4  = (idx & 31) * 4;
        const float* cr = Csh + r * 132 + c4;
        *(float4*)(C + (size_t)(bm + r) * DDIM + bn + c4) =
            make_float4(cr[0], cr[1], cr[2], cr[3]);
    }
}

#define SMEM_DYN3 (NSTAGE * 4 * TILE_B)   // 98304
#define SMEM_DYN2 (NSTAGE * 3 * TILE_B)   // 73728

// ---------------------------------------------------------------------------
// Per-node linear attention via 8x8 score matrix; emits fp16 attn for Wf GEMM.
// ---------------------------------------------------------------------------
#define PADR 68

__global__ __launch_bounds__(256) void attn2(const float* __restrict__ q,
                                             const float* __restrict__ k,
                                             const float* __restrict__ v,
                                             __half* __restrict__ ahi) {
    __shared__ float sq[4][NHEADS * PADR];
    __shared__ float sk[4][NHEADS * PADR];
    __shared__ float sv[4][NHEADS * PADR];
    __shared__ float Ss[4][NHEADS * NHEADS];

    const int tid = threadIdx.x;
    const int ln  = tid >> 6;
    const int t   = tid & 63;
    const size_t base = ((size_t)blockIdx.x * 4 + ln) * DDIM;

#pragma unroll
    for (int c = 0; c < 2; ++c) {
        const int i = t * 4 + c * 256;
        const int h = i >> 6;
        const int d = i & 63;
        *(float4*)&sq[ln][h * PADR + d] = *(const float4*)(q + base + i);
        *(float4*)&sk[ln][h * PADR + d] = *(const float4*)(k + base + i);
        *(float4*)&sv[ln][h * PADR + d] = *(const float4*)(v + base + i);
    }
    __syncthreads();

    {
        const float* qp = &sq[ln][(t >> 3) * PADR];
        const float* kp = &sk[ln][(t & 7) * PADR];
        float s = 0.0f;
#pragma unroll
        for (int d = 0; d < HDIM; ++d) s = fmaf(qp[d], kp[d], s);
        Ss[ln][t] = s;
    }
    __syncthreads();

    {
        const int e = t;
#pragma unroll
        for (int h = 0; h < NHEADS; ++h) {
            float num = 0.0f, den = 0.0f;
#pragma unroll
            for (int hp = 0; hp < NHEADS; ++hp) {
                const float Sv = Ss[ln][h * NHEADS + hp];
                den += Sv;
                num = fmaf(Sv, sv[ln][hp * PADR + e], num);
            }
            ahi[base + h * HDIM + e] = __float2half(num / den);
        }
    }
}

// ---------------------------------------------------------------------------
// Fused residual + LayerNorm, one warp per row, float4 vectorized.
// ---------------------------------------------------------------------------
__global__ __launch_bounds__(256) void ln_kernel(const float* __restrict__ h,
                                                 const float* __restrict__ fh,
                                                 const float* __restrict__ gamma,
                                                 const float* __restrict__ beta,
                                                 float* __restrict__ out) {
    const int row  = (blockIdx.x * blockDim.x + threadIdx.x) >> 5;
    const int lane = threadIdx.x & 31;
    if (row >= NROWS) return;

    const size_t b4 = (size_t)row * 128;   // float4 base
    float4 x[4];
    float s = 0.0f;
#pragma unroll
    for (int i = 0; i < 4; ++i) {
        const int c = lane + i * 32;
        float4 a = ((const float4*)h)[b4 + c];
        float4 f = ((const float4*)fh)[b4 + c];
        x[i].x = a.x + f.x; x[i].y = a.y + f.y;
        x[i].z = a.z + f.z; x[i].w = a.w + f.w;
        s += x[i].x + x[i].y + x[i].z + x[i].w;
    }
#pragma unroll
    for (int off = 16; off > 0; off >>= 1) s += __shfl_xor_sync(0xffffffffu, s, off);
    const float mu = s * (1.0f / DDIM);

    float var = 0.0f;
#pragma unroll
    for (int i = 0; i < 4; ++i) {
        float dx = x[i].x - mu, dy = x[i].y - mu, dz = x[i].z - mu, dw = x[i].w - mu;
        var = fmaf(dx, dx, var); var = fmaf(dy, dy, var);
        var = fmaf(dz, dz, var); var = fmaf(dw, dw, var);
    }
#pragma unroll
    for (int off = 16; off > 0; off >>= 1) var += __shfl_xor_sync(0xffffffffu, var, off);
    var *= (1.0f / DDIM);

    const float r = rsqrtf(var + LN_EPS);
#pragma unroll
    for (int i = 0; i < 4; ++i) {
        const int c = lane + i * 32;
        float4 g = ((const float4*)gamma)[c];
        float4 bt = ((const float4*)beta)[c];
        float4 o;
        o.x = (x[i].x - mu) * r * g.x + bt.x;
        o.y = (x[i].y - mu) * r * g.y + bt.y;
        o.z = (x[i].z - mu) * r * g.z + bt.z;
        o.w = (x[i].w - mu) * r * g.w + bt.w;
        ((float4*)out)[b4 + c] = o;
    }
}

// ---------------------------------------------------------------------------
// kernel_launch
// ---------------------------------------------------------------------------
extern "C" void kernel_launch(void* const* d_in, const int* in_sizes, int n_in,
                              void* d_out, int out_size) {
    const float* h     = (const float*)d_in[0];
    const float* Wq    = (const float*)d_in[1];
    const float* Wk    = (const float*)d_in[2];
    const float* Wv    = (const float*)d_in[3];
    const float* Wf    = (const float*)d_in[4];
    const float* gamma = (const float*)d_in[5];
    const float* beta  = (const float*)d_in[6];

    float* out = (float*)d_out;
    float* q   = out + (size_t)NROWS * DDIM;
    float* k   = out + 2 * (size_t)NROWS * DDIM;
    float* v   = out + 3 * (size_t)NROWS * DDIM;

    void *hhi, *hlo, *athi, *wthi, *wtlo, *fhp;
    cudaGetSymbolAddress(&hhi, g_h_hi);
    cudaGetSymbolAddress(&hlo, g_h_lo);
    cudaGetSymbolAddress(&athi, g_at_hi);
    cudaGetSymbolAddress(&wthi, g_wt_hi);
    cudaGetSymbolAddress(&wtlo, g_wt_lo);
    cudaGetSymbolAddress(&fhp, g_fh);

    cudaFuncSetAttribute(gemm_mma<3, true>,
                         cudaFuncAttributeMaxDynamicSharedMemorySize, SMEM_DYN3);
    cudaFuncSetAttribute(gemm_mma<2, false>,
                         cudaFuncAttributeMaxDynamicSharedMemorySize, SMEM_DYN2);

    __half* Hhi = (__half*)hhi;
    __half* Hlo = (__half*)hlo;
    __half* Ath = (__half*)athi;
    __half* WTh = (__half*)wthi;
    __half* WTl = (__half*)wtlo;

    conv_h<<<(NROWS * DDIM) / 4 / 256, 256>>>(h, Hhi, Hlo);
    conv_wt<<<dim3(16, 16, 4), dim3(32, 8)>>>(Wq, Wk, Wv, Wf, WTh, WTl);

    const size_t WSZ = (size_t)DDIM * DDIM;

    // fused q,k,v projections (z = 0,1,2); outputs are contiguous slabs
    gemm_mma<3, true><<<dim3(4, 256, 3), 256, SMEM_DYN3>>>(Hhi, Hlo, WTh, WTl, q);

    attn2<<<NROWS / 4, 256>>>(q, k, v, Ath);

    // Wf GEMM: 2-term (A = fp16 attn; B split hi/lo)
    gemm_mma<2, false><<<dim3(4, 256, 1), 256, SMEM_DYN2>>>(
        Ath, Ath, WTh + 3 * WSZ, WTl + 3 * WSZ, (float*)fhp);

    ln_kernel<<<(NROWS * 32) / 256, 256>>>(h, (const float*)fhp, gamma, beta, out);
}

// round 9
// speedup vs baseline: 1.6825x; 1.2485x over previous
#include <cuda_runtime.h>
#include <cuda_fp16.h>
#include <cstdint>

// Problem constants (AGTLayer: N=32768, D=512, H=8, HD=64)
#define NROWS 32768
#define DDIM  512
#define NHEADS 8
#define HDIM  64
#define LN_EPS 1e-5f

// ---------------------------------------------------------------------------
// Scratch (__device__ globals; allocation-free rule)
// ---------------------------------------------------------------------------
__device__ __half g_h_hi[(size_t)NROWS * DDIM];
__device__ __half g_at_hi[(size_t)NROWS * DDIM];
__device__ __half g_wt_hi[4 * DDIM * DDIM];   // transposed: Wt[n][k]
__device__ __half g_wt_lo[4 * DDIM * DDIM];
__device__ float g_fh[(size_t)NROWS * DDIM];

// ---------------------------------------------------------------------------
// helpers
// ---------------------------------------------------------------------------
__device__ __forceinline__ uint32_t s2u(const void* p) {
    uint32_t a;
    asm("{ .reg .u64 t; cvta.to.shared.u64 t, %1; cvt.u32.u64 %0, t; }"
        : "=r"(a) : "l"(p));
    return a;
}

__device__ __forceinline__ void cpasync16(uint32_t dst, const void* src) {
    asm volatile("cp.async.cg.shared.global [%0], [%1], 16;" :: "r"(dst), "l"(src));
}
__device__ __forceinline__ void cp_commit() {
    asm volatile("cp.async.commit_group;" ::: "memory");
}
__device__ __forceinline__ void cp_wait1() {
    asm volatile("cp.async.wait_group 1;" ::: "memory");
}

__device__ __forceinline__ void ldm_x4(uint32_t* r, uint32_t addr) {
    asm volatile("ldmatrix.sync.aligned.m8n8.x4.shared.b16 {%0,%1,%2,%3}, [%4];"
                 : "=r"(r[0]), "=r"(r[1]), "=r"(r[2]), "=r"(r[3]) : "r"(addr));
}

__device__ __forceinline__ void mma16816(float* c, const uint32_t* a, const uint32_t* b) {
    asm volatile(
        "mma.sync.aligned.m16n8k16.row.col.f32.f16.f16.f32 "
        "{%0,%1,%2,%3}, {%4,%5,%6,%7}, {%8,%9}, {%0,%1,%2,%3};"
        : "+f"(c[0]), "+f"(c[1]), "+f"(c[2]), "+f"(c[3])
        : "r"(a[0]), "r"(a[1]), "r"(a[2]), "r"(a[3]), "r"(b[0]), "r"(b[1]));
}

// swizzled smem byte offset within a tile: rows of 64 B (32 halves), 4 16B segs
__device__ __forceinline__ uint32_t swz(int row, int seg) {
    return (uint32_t)(row * 64 + ((seg ^ ((row >> 1) & 3)) << 4));
}

// ---------------------------------------------------------------------------
// Conversion: h fp32 -> fp16 (single, QKV A operand)
// ---------------------------------------------------------------------------
__global__ __launch_bounds__(256) void conv_h(const float* __restrict__ src,
                                              __half* __restrict__ hi) {
    const size_t i4 = (size_t)blockIdx.x * 256 + threadIdx.x;
    float4 x = ((const float4*)src)[i4];
    __half2 h01, h23;
    h01.x = __float2half(x.x); h01.y = __float2half(x.y);
    h23.x = __float2half(x.z); h23.y = __float2half(x.w);
    ((__half2*)hi)[i4 * 2]     = h01;
    ((__half2*)hi)[i4 * 2 + 1] = h23;
}

// ---------------------------------------------------------------------------
// Conversion + transpose: W[k][n] fp32 -> Wt[n][k] fp16 hi/lo (4 matrices)
// ---------------------------------------------------------------------------
__global__ __launch_bounds__(256) void conv_wt(const float* __restrict__ W0,
                                               const float* __restrict__ W1,
                                               const float* __restrict__ W2,
                                               const float* __restrict__ W3,
                                               __half* __restrict__ hi,
                                               __half* __restrict__ lo) {
    const float* W = (blockIdx.z == 0) ? W0 : (blockIdx.z == 1) ? W1
                     : (blockIdx.z == 2) ? W2 : W3;
    __shared__ float t[32][33];
    const int tx = threadIdx.x, ty = threadIdx.y;  // 32 x 8
    const int n0 = blockIdx.x * 32, k0 = blockIdx.y * 32;
#pragma unroll
    for (int i = 0; i < 4; ++i)
        t[ty + i * 8][tx] = W[(size_t)(k0 + ty + i * 8) * DDIM + n0 + tx];
    __syncthreads();
    const size_t base = (size_t)blockIdx.z * DDIM * DDIM;
#pragma unroll
    for (int i = 0; i < 4; ++i) {
        const int n = n0 + ty + i * 8;
        const int k = k0 + tx;
        const float v = t[tx][ty + i * 8];
        const __half hv = __float2half(v);
        hi[base + (size_t)n * DDIM + k] = hv;
        lo[base + (size_t)n * DDIM + k] = __float2half(v - __half2float(hv));
    }
}

// ---------------------------------------------------------------------------
// HMMA 2-term split GEMM: C[M,512] fp32 = A @ Wt^T = Ah*Bh + Ah*Bl
//   A single fp16 [M][512]; B (=Wt) hi/lo fp16 [512 n][512 k]
// CTA 128x128, BK=32, 8 warps (64x32), 3-stage cp.async, swizzled + ldmatrix.
// QKV=true: gridDim.z selects weight/output slab; relu for z<2.
// ---------------------------------------------------------------------------
#define TILE_B   (128 * 64)              // 8192 B per operand tile
#define NSTAGE   3
#define STAGE_B  (3 * TILE_B)            // Ah, Bh, Bl = 24576 B
#define SMEM_DYN (NSTAGE * STAGE_B)      // 73728 B -> 2 CTAs/SM

template <bool QKV>
__global__ __launch_bounds__(256) void gemm_mma(const __half* __restrict__ Ah,
                                                const __half* __restrict__ Bh0,
                                                const __half* __restrict__ Bl0,
                                                float* __restrict__ C0) {
    extern __shared__ char dsm[];
    const uint32_t sb = s2u(dsm);

    const int tid  = threadIdx.x;
    const int wid  = tid >> 5;
    const int lane = tid & 31;
    const int bm   = blockIdx.y * 128;
    const int bn   = blockIdx.x * 128;

    const size_t zoffW = QKV ? (size_t)blockIdx.z * DDIM * DDIM : 0;
    const size_t zoffC = QKV ? (size_t)blockIdx.z * NROWS * DDIM : 0;
    const __half* Bh = Bh0 + zoffW;
    const __half* Bl = Bl0 + zoffW;
    float* C = C0 + zoffC;
    const bool relu = QKV ? (blockIdx.z < 2) : false;

    const int wm = (wid & 1) * 64;   // warp m offset
    const int wn = (wid >> 1) * 32;  // warp n offset

    float acc[4][4][4];
#pragma unroll
    for (int i = 0; i < 4; ++i)
#pragma unroll
        for (int j = 0; j < 4; ++j)
#pragma unroll
            for (int r = 0; r < 4; ++r) acc[i][j][r] = 0.0f;

    const __half* srcs[3] = {Ah, Bh, Bl};
    const int rws[3] = {bm, bn, bn};

    auto load_stage = [&](int stage, int kc) {
        const uint32_t s0 = sb + stage * STAGE_B;
#pragma unroll
        for (int tile = 0; tile < 3; ++tile) {
#pragma unroll
            for (int it = 0; it < 2; ++it) {
                const int ch  = tid + it * 256;     // 0..511
                const int row = ch >> 2;
                const int seg = ch & 3;
                cpasync16(s0 + tile * TILE_B + swz(row, seg),
                          srcs[tile] + (size_t)(rws[tile] + row) * DDIM + kc + seg * 8);
            }
        }
    };

    // prologue: stages 0,1
    load_stage(0, 0);
    cp_commit();
    load_stage(1, 32);
    cp_commit();

    // ldmatrix lane roles
    const int a_row = lane & 15;
    const int a_sg  = lane >> 4;
    const int b_row = ((lane >> 4) & 1) * 8 + (lane & 7);
    const int b_sg  = (lane >> 3) & 1;

    for (int kt = 0; kt < 16; ++kt) {
        cp_wait1();
        __syncthreads();

        if (kt + 2 < 16) load_stage((kt + 2) % NSTAGE, (kt + 2) * 32);
        cp_commit();

        const uint32_t s0  = sb + (kt % NSTAGE) * STAGE_B;
        const uint32_t aho = s0;
        const uint32_t bho = s0 + TILE_B;
        const uint32_t blo = s0 + 2 * TILE_B;

#pragma unroll
        for (int s = 0; s < 2; ++s) {
            const int ksg = s * 2;
            uint32_t bh[4][2], bl[4][2];
#pragma unroll
            for (int jp = 0; jp < 2; ++jp) {
                const uint32_t ba = swz(wn + jp * 16 + b_row, ksg + b_sg);
                uint32_t r[4];
                ldm_x4(r, bho + ba);
                bh[jp * 2][0] = r[0]; bh[jp * 2][1] = r[1];
                bh[jp * 2 + 1][0] = r[2]; bh[jp * 2 + 1][1] = r[3];
                ldm_x4(r, blo + ba);
                bl[jp * 2][0] = r[0]; bl[jp * 2][1] = r[1];
                bl[jp * 2 + 1][0] = r[2]; bl[jp * 2 + 1][1] = r[3];
            }
#pragma unroll
            for (int i = 0; i < 4; ++i) {
                const uint32_t aa = swz(wm + i * 16 + a_row, ksg + a_sg);
                uint32_t ah[4];
                ldm_x4(ah, aho + aa);
#pragma unroll
                for (int j = 0; j < 4; ++j) {
                    mma16816(acc[i][j], ah, bh[j]);
                    mma16816(acc[i][j], ah, bl[j]);
                }
            }
        }
    }

    __syncthreads();

    // epilogue: acc -> padded smem -> coalesced fp32 stores
    const int r4 = lane >> 2;
    const int c2 = (lane & 3) * 2;
    float* Csh = (float*)dsm;   // 128 x 132 floats = 67584 B
#pragma unroll
    for (int i = 0; i < 4; ++i) {
#pragma unroll
        for (int j = 0; j < 4; ++j) {
            const int row = wm + i * 16 + r4;
            const int col = wn + j * 8 + c2;
            float d0 = acc[i][j][0], d1 = acc[i][j][1];
            float d2 = acc[i][j][2], d3 = acc[i][j][3];
            if (relu) {
                d0 = fmaxf(d0, 0.0f); d1 = fmaxf(d1, 0.0f);
                d2 = fmaxf(d2, 0.0f); d3 = fmaxf(d3, 0.0f);
            }
            *(float2*)&Csh[row * 132 + col]       = make_float2(d0, d1);
            *(float2*)&Csh[(row + 8) * 132 + col] = make_float2(d2, d3);
        }
    }
    __syncthreads();

#pragma unroll
    for (int i = 0; i < 16; ++i) {
        const int idx = tid + i * 256;   // float4 id, 0..4095
        const int r   = idx >> 5;
        const int c4  = (idx & 31) * 4;
        const float* cr = Csh + r * 132 + c4;
        *(float4*)(C + (size_t)(bm + r) * DDIM + bn + c4) =
            make_float4(cr[0], cr[1], cr[2], cr[3]);
    }
}

// ---------------------------------------------------------------------------
// Per-node linear attention via 8x8 score matrix; emits fp16 attn for Wf GEMM.
// 4 nodes/block, 64 threads/node. float4 smem dots + register-cached sv.
// ---------------------------------------------------------------------------
#define PADR 68

__global__ __launch_bounds__(256) void attn2(const float* __restrict__ q,
                                             const float* __restrict__ k,
                                             const float* __restrict__ v,
                                             __half* __restrict__ ahi) {
    __shared__ float sq[4][NHEADS * PADR];
    __shared__ float sk[4][NHEADS * PADR];
    __shared__ float sv[4][NHEADS * PADR];
    __shared__ float Ss[4][NHEADS * NHEADS];

    const int tid = threadIdx.x;
    const int ln  = tid >> 6;
    const int t   = tid & 63;
    const size_t base = ((size_t)blockIdx.x * 4 + ln) * DDIM;

#pragma unroll
    for (int c = 0; c < 2; ++c) {
        const int i = t * 4 + c * 256;
        const int h = i >> 6;
        const int d = i & 63;
        *(float4*)&sq[ln][h * PADR + d] = *(const float4*)(q + base + i);
        *(float4*)&sk[ln][h * PADR + d] = *(const float4*)(k + base + i);
        *(float4*)&sv[ln][h * PADR + d] = *(const float4*)(v + base + i);
    }
    __syncthreads();

    {
        const float4* qp = (const float4*)&sq[ln][(t >> 3) * PADR];
        const float4* kp = (const float4*)&sk[ln][(t & 7) * PADR];
        float s = 0.0f;
#pragma unroll
        for (int d4 = 0; d4 < 16; ++d4) {
            float4 a = qp[d4], b = kp[d4];
            s = fmaf(a.x, b.x, s);
            s = fmaf(a.y, b.y, s);
            s = fmaf(a.z, b.z, s);
            s = fmaf(a.w, b.w, s);
        }
        Ss[ln][t] = s;
    }
    __syncthreads();

    {
        const int e = t;
        float sval[NHEADS];
#pragma unroll
        for (int hp = 0; hp < NHEADS; ++hp) sval[hp] = sv[ln][hp * PADR + e];
#pragma unroll
        for (int h = 0; h < NHEADS; ++h) {
            float num = 0.0f, den = 0.0f;
#pragma unroll
            for (int hp = 0; hp < NHEADS; ++hp) {
                const float Sv = Ss[ln][h * NHEADS + hp];
                den += Sv;
                num = fmaf(Sv, sval[hp], num);
            }
            ahi[base + h * HDIM + e] = __float2half(num / den);
        }
    }
}

// ---------------------------------------------------------------------------
// Fused residual + LayerNorm, one warp per row, float4 vectorized.
// ---------------------------------------------------------------------------
__global__ __launch_bounds__(256) void ln_kernel(const float* __restrict__ h,
                                                 const float* __restrict__ fh,
                                                 const float* __restrict__ gamma,
                                                 const float* __restrict__ beta,
                                                 float* __restrict__ out) {
    const int row  = (blockIdx.x * blockDim.x + threadIdx.x) >> 5;
    const int lane = threadIdx.x & 31;
    if (row >= NROWS) return;

    const size_t b4 = (size_t)row * 128;   // float4 base
    float4 x[4];
    float s = 0.0f;
#pragma unroll
    for (int i = 0; i < 4; ++i) {
        const int c = lane + i * 32;
        float4 a = ((const float4*)h)[b4 + c];
        float4 f = ((const float4*)fh)[b4 + c];
        x[i].x = a.x + f.x; x[i].y = a.y + f.y;
        x[i].z = a.z + f.z; x[i].w = a.w + f.w;
        s += x[i].x + x[i].y + x[i].z + x[i].w;
    }
#pragma unroll
    for (int off = 16; off > 0; off >>= 1) s += __shfl_xor_sync(0xffffffffu, s, off);
    const float mu = s * (1.0f / DDIM);

    float var = 0.0f;
#pragma unroll
    for (int i = 0; i < 4; ++i) {
        float dx = x[i].x - mu, dy = x[i].y - mu, dz = x[i].z - mu, dw = x[i].w - mu;
        var = fmaf(dx, dx, var); var = fmaf(dy, dy, var);
        var = fmaf(dz, dz, var); var = fmaf(dw, dw, var);
    }
#pragma unroll
    for (int off = 16; off > 0; off >>= 1) var += __shfl_xor_sync(0xffffffffu, var, off);
    var *= (1.0f / DDIM);

    const float r = rsqrtf(var + LN_EPS);
#pragma unroll
    for (int i = 0; i < 4; ++i) {
        const int c = lane + i * 32;
        float4 g = ((const float4*)gamma)[c];
        float4 bt = ((const float4*)beta)[c];
        float4 o;
        o.x = (x[i].x - mu) * r * g.x + bt.x;
        o.y = (x[i].y - mu) * r * g.y + bt.y;
        o.z = (x[i].z - mu) * r * g.z + bt.z;
        o.w = (x[i].w - mu) * r * g.w + bt.w;
        ((float4*)out)[b4 + c] = o;
    }
}

// ---------------------------------------------------------------------------
// kernel_launch
// ---------------------------------------------------------------------------
extern "C" void kernel_launch(void* const* d_in, const int* in_sizes, int n_in,
                              void* d_out, int out_size) {
    const float* h     = (const float*)d_in[0];
    const float* Wq    = (const float*)d_in[1];
    const float* Wk    = (const float*)d_in[2];
    const float* Wv    = (const float*)d_in[3];
    const float* Wf    = (const float*)d_in[4];
    const float* gamma = (const float*)d_in[5];
    const float* beta  = (const float*)d_in[6];

    float* out = (float*)d_out;
    float* q   = out + (size_t)NROWS * DDIM;
    float* k   = out + 2 * (size_t)NROWS * DDIM;
    float* v   = out + 3 * (size_t)NROWS * DDIM;

    void *hhi, *athi, *wthi, *wtlo, *fhp;
    cudaGetSymbolAddress(&hhi, g_h_hi);
    cudaGetSymbolAddress(&athi, g_at_hi);
    cudaGetSymbolAddress(&wthi, g_wt_hi);
    cudaGetSymbolAddress(&wtlo, g_wt_lo);
    cudaGetSymbolAddress(&fhp, g_fh);

    cudaFuncSetAttribute(gemm_mma<true>,
                         cudaFuncAttributeMaxDynamicSharedMemorySize, SMEM_DYN);
    cudaFuncSetAttribute(gemm_mma<false>,
                         cudaFuncAttributeMaxDynamicSharedMemorySize, SMEM_DYN);

    __half* Hhi = (__half*)hhi;
    __half* Ath = (__half*)athi;
    __half* WTh = (__half*)wthi;
    __half* WTl = (__half*)wtlo;

    conv_h<<<(NROWS * DDIM) / 4 / 256, 256>>>(h, Hhi);
    conv_wt<<<dim3(16, 16, 4), dim3(32, 8)>>>(Wq, Wk, Wv, Wf, WTh, WTl);

    const size_t WSZ = (size_t)DDIM * DDIM;

    // fused q,k,v projections (z = 0,1,2); outputs are contiguous slabs
    gemm_mma<true><<<dim3(4, 256, 3), 256, SMEM_DYN>>>(Hhi, WTh, WTl, q);

    attn2<<<NROWS / 4, 256>>>(q, k, v, Ath);

    // Wf GEMM: 2-term (A = fp16 attn; B split hi/lo)
    gemm_mma<false><<<dim3(4, 256, 1), 256, SMEM_DYN>>>(
        Ath, WTh + 3 * WSZ, WTl + 3 * WSZ, (float*)fhp);

    ln_kernel<<<(NROWS * 32) / 256, 256>>>(h, (const float*)fhp, gamma, beta, out);
}

// round 10
// speedup vs baseline: 1.7644x; 1.0487x over previous
#include <cuda_runtime.h>
#include <cuda_fp16.h>
#include <cstdint>

// Problem constants (AGTLayer: N=32768, D=512, H=8, HD=64)
#define NROWS 32768
#define DDIM  512
#define NHEADS 8
#define HDIM  64
#define LN_EPS 1e-5f

// ---------------------------------------------------------------------------
// Scratch (__device__ globals; allocation-free rule)
// ---------------------------------------------------------------------------
__device__ __half g_h_hi[(size_t)NROWS * DDIM];
__device__ __half g_qkvh[3 * (size_t)NROWS * DDIM];  // fp16 copies of q,k,v
__device__ __half g_at_hi[(size_t)NROWS * DDIM];
__device__ __half g_wt_hi[4 * DDIM * DDIM];          // transposed: Wt[n][k]
__device__ __half g_wt_lo[4 * DDIM * DDIM];
__device__ float g_fh[(size_t)NROWS * DDIM];

// ---------------------------------------------------------------------------
// helpers
// ---------------------------------------------------------------------------
__device__ __forceinline__ uint32_t s2u(const void* p) {
    uint32_t a;
    asm("{ .reg .u64 t; cvta.to.shared.u64 t, %1; cvt.u32.u64 %0, t; }"
        : "=r"(a) : "l"(p));
    return a;
}

__device__ __forceinline__ void cpasync16(uint32_t dst, const void* src) {
    asm volatile("cp.async.cg.shared.global [%0], [%1], 16;" :: "r"(dst), "l"(src));
}
__device__ __forceinline__ void cp_commit() {
    asm volatile("cp.async.commit_group;" ::: "memory");
}
__device__ __forceinline__ void cp_wait2() {
    asm volatile("cp.async.wait_group 2;" ::: "memory");
}

__device__ __forceinline__ void ldm_x4(uint32_t* r, uint32_t addr) {
    asm volatile("ldmatrix.sync.aligned.m8n8.x4.shared.b16 {%0,%1,%2,%3}, [%4];"
                 : "=r"(r[0]), "=r"(r[1]), "=r"(r[2]), "=r"(r[3]) : "r"(addr));
}

__device__ __forceinline__ void mma16816(float* c, const uint32_t* a, const uint32_t* b) {
    asm volatile(
        "mma.sync.aligned.m16n8k16.row.col.f32.f16.f16.f32 "
        "{%0,%1,%2,%3}, {%4,%5,%6,%7}, {%8,%9}, {%0,%1,%2,%3};"
        : "+f"(c[0]), "+f"(c[1]), "+f"(c[2]), "+f"(c[3])
        : "r"(a[0]), "r"(a[1]), "r"(a[2]), "r"(a[3]), "r"(b[0]), "r"(b[1]));
}

// swizzled smem byte offset within a tile: rows of 64 B (32 halves), 4 16B segs
__device__ __forceinline__ uint32_t swz(int row, int seg) {
    return (uint32_t)(row * 64 + ((seg ^ ((row >> 1) & 3)) << 4));
}

// ---------------------------------------------------------------------------
// Conversion: h fp32 -> fp16 (single, QKV A operand)
// ---------------------------------------------------------------------------
__global__ __launch_bounds__(256) void conv_h(const float* __restrict__ src,
                                              __half* __restrict__ hi) {
    const size_t i4 = (size_t)blockIdx.x * 256 + threadIdx.x;
    float4 x = ((const float4*)src)[i4];
    __half2 h01, h23;
    h01.x = __float2half(x.x); h01.y = __float2half(x.y);
    h23.x = __float2half(x.z); h23.y = __float2half(x.w);
    ((__half2*)hi)[i4 * 2]     = h01;
    ((__half2*)hi)[i4 * 2 + 1] = h23;
}

// ---------------------------------------------------------------------------
// Conversion + transpose: W[k][n] fp32 -> Wt[n][k] fp16 hi/lo (4 matrices)
// ---------------------------------------------------------------------------
__global__ __launch_bounds__(256) void conv_wt(const float* __restrict__ W0,
                                               const float* __restrict__ W1,
                                               const float* __restrict__ W2,
                                               const float* __restrict__ W3,
                                               __half* __restrict__ hi,
                                               __half* __restrict__ lo) {
    const float* W = (blockIdx.z == 0) ? W0 : (blockIdx.z == 1) ? W1
                     : (blockIdx.z == 2) ? W2 : W3;
    __shared__ float t[32][33];
    const int tx = threadIdx.x, ty = threadIdx.y;  // 32 x 8
    const int n0 = blockIdx.x * 32, k0 = blockIdx.y * 32;
#pragma unroll
    for (int i = 0; i < 4; ++i)
        t[ty + i * 8][tx] = W[(size_t)(k0 + ty + i * 8) * DDIM + n0 + tx];
    __syncthreads();
    const size_t base = (size_t)blockIdx.z * DDIM * DDIM;
#pragma unroll
    for (int i = 0; i < 4; ++i) {
        const int n = n0 + ty + i * 8;
        const int k = k0 + tx;
        const float v = t[tx][ty + i * 8];
        const __half hv = __float2half(v);
        hi[base + (size_t)n * DDIM + k] = hv;
        lo[base + (size_t)n * DDIM + k] = __float2half(v - __half2float(hv));
    }
}

// ---------------------------------------------------------------------------
// HMMA split GEMM: C[M,512] fp32 = A @ Wt^T
//   TERMS=2: C = Ah*Bh + Ah*Bl  (tiles Ah,Bh,Bl)  -- QKV
//   TERMS=1: C = Ah*Bh          (tiles Ah,Bh)     -- Wf
// CTA 128x128, BK=32, 8 warps (64x32), 4-stage cp.async, swizzled + ldmatrix.
// QKV=true: gridDim.z selects weight/output slab; relu for z<2; also emits
// fp16 copy of C to Ch (for the attention kernel).
// ---------------------------------------------------------------------------
#define TILE_B   (128 * 64)              // 8192 B per operand tile
#define NSTAGE   4

template <int TERMS, bool QKV>
__global__ __launch_bounds__(256) void gemm_mma(const __half* __restrict__ Ah,
                                                const __half* __restrict__ Bh0,
                                                const __half* __restrict__ Bl0,
                                                float* __restrict__ C0,
                                                __half* __restrict__ Ch0) {
    constexpr int NTILES  = TERMS + 1;
    constexpr int STAGE_B = NTILES * TILE_B;

    extern __shared__ char dsm[];
    const uint32_t sb = s2u(dsm);

    const int tid  = threadIdx.x;
    const int wid  = tid >> 5;
    const int lane = tid & 31;
    const int bm   = blockIdx.y * 128;
    const int bn   = blockIdx.x * 128;

    const size_t zoffW = QKV ? (size_t)blockIdx.z * DDIM * DDIM : 0;
    const size_t zoffC = QKV ? (size_t)blockIdx.z * NROWS * DDIM : 0;
    const __half* Bh = Bh0 + zoffW;
    const __half* Bl = Bl0 + zoffW;
    float* C = C0 + zoffC;
    __half* Ch = QKV ? (Ch0 + zoffC) : nullptr;
    const bool relu = QKV ? (blockIdx.z < 2) : false;

    const int wm = (wid & 1) * 64;   // warp m offset
    const int wn = (wid >> 1) * 32;  // warp n offset

    float acc[4][4][4];
#pragma unroll
    for (int i = 0; i < 4; ++i)
#pragma unroll
        for (int j = 0; j < 4; ++j)
#pragma unroll
            for (int r = 0; r < 4; ++r) acc[i][j][r] = 0.0f;

    const __half* srcs[NTILES];
    int rws[NTILES];
    srcs[0] = Ah; rws[0] = bm;
    srcs[1] = Bh; rws[1] = bn;
    if (TERMS == 2) { srcs[2] = Bl; rws[2] = bn; }

    auto load_stage = [&](int stage, int kc) {
        const uint32_t s0 = sb + stage * STAGE_B;
#pragma unroll
        for (int tile = 0; tile < NTILES; ++tile) {
#pragma unroll
            for (int it = 0; it < 2; ++it) {
                const int ch  = tid + it * 256;     // 0..511
                const int row = ch >> 2;
                const int seg = ch & 3;
                cpasync16(s0 + tile * TILE_B + swz(row, seg),
                          srcs[tile] + (size_t)(rws[tile] + row) * DDIM + kc + seg * 8);
            }
        }
    };

    // prologue: stages 0,1,2
#pragma unroll
    for (int s = 0; s < 3; ++s) {
        load_stage(s, s * 32);
        cp_commit();
    }

    // ldmatrix lane roles
    const int a_row = lane & 15;
    const int a_sg  = lane >> 4;
    const int b_row = ((lane >> 4) & 1) * 8 + (lane & 7);
    const int b_sg  = (lane >> 3) & 1;

    for (int kt = 0; kt < 16; ++kt) {
        cp_wait2();          // stage kt resident (<=2 newer groups pending)
        __syncthreads();     // stage (kt+3)%4 free (computed at kt-1)

        if (kt + 3 < 16) load_stage((kt + 3) & (NSTAGE - 1), (kt + 3) * 32);
        cp_commit();

        const uint32_t s0  = sb + (kt & (NSTAGE - 1)) * STAGE_B;
        const uint32_t aho = s0;
        const uint32_t bho = s0 + TILE_B;
        const uint32_t blo = s0 + 2 * TILE_B;   // TERMS==2 only

#pragma unroll
        for (int s = 0; s < 2; ++s) {
            const int ksg = s * 2;
            uint32_t bh[4][2], bl[4][2];
#pragma unroll
            for (int jp = 0; jp < 2; ++jp) {
                const uint32_t ba = swz(wn + jp * 16 + b_row, ksg + b_sg);
                uint32_t r[4];
                ldm_x4(r, bho + ba);
                bh[jp * 2][0] = r[0]; bh[jp * 2][1] = r[1];
                bh[jp * 2 + 1][0] = r[2]; bh[jp * 2 + 1][1] = r[3];
                if (TERMS == 2) {
                    ldm_x4(r, blo + ba);
                    bl[jp * 2][0] = r[0]; bl[jp * 2][1] = r[1];
                    bl[jp * 2 + 1][0] = r[2]; bl[jp * 2 + 1][1] = r[3];
                }
            }
#pragma unroll
            for (int i = 0; i < 4; ++i) {
                const uint32_t aa = swz(wm + i * 16 + a_row, ksg + a_sg);
                uint32_t ah[4];
                ldm_x4(ah, aho + aa);
#pragma unroll
                for (int j = 0; j < 4; ++j) {
                    mma16816(acc[i][j], ah, bh[j]);
                    if (TERMS == 2) mma16816(acc[i][j], ah, bl[j]);
                }
            }
        }
    }

    __syncthreads();

    // epilogue: acc -> padded smem -> coalesced stores (fp32 + optional fp16)
    const int r4 = lane >> 2;
    const int c2 = (lane & 3) * 2;
    float* Csh = (float*)dsm;   // 128 x 132 floats = 67584 B
#pragma unroll
    for (int i = 0; i < 4; ++i) {
#pragma unroll
        for (int j = 0; j < 4; ++j) {
            const int row = wm + i * 16 + r4;
            const int col = wn + j * 8 + c2;
            float d0 = acc[i][j][0], d1 = acc[i][j][1];
            float d2 = acc[i][j][2], d3 = acc[i][j][3];
            if (relu) {
                d0 = fmaxf(d0, 0.0f); d1 = fmaxf(d1, 0.0f);
                d2 = fmaxf(d2, 0.0f); d3 = fmaxf(d3, 0.0f);
            }
            *(float2*)&Csh[row * 132 + col]       = make_float2(d0, d1);
            *(float2*)&Csh[(row + 8) * 132 + col] = make_float2(d2, d3);
        }
    }
    __syncthreads();

#pragma unroll
    for (int i = 0; i < 16; ++i) {
        const int idx = tid + i * 256;   // float4 id, 0..4095
        const int r   = idx >> 5;
        const int c4  = (idx & 31) * 4;
        const float* cr = Csh + r * 132 + c4;
        float4 v4 = make_float4(cr[0], cr[1], cr[2], cr[3]);
        *(float4*)(C + (size_t)(bm + r) * DDIM + bn + c4) = v4;
        if (QKV) {
            __half2 p0, p1;
            p0.x = __float2half(v4.x); p0.y = __float2half(v4.y);
            p1.x = __float2half(v4.z); p1.y = __float2half(v4.w);
            __half2* cp = (__half2*)(Ch + (size_t)(bm + r) * DDIM + bn + c4);
            cp[0] = p0;
            cp[1] = p1;
        }
    }
}

#define SMEM_DYN_QKV (NSTAGE * 3 * TILE_B)   // 98304
#define SMEM_DYN_WF  69632                   // >= 2-tile stages (65536) and Csh (67584)

// ---------------------------------------------------------------------------
// Per-node linear attention via 8x8 score matrix, fp16 inputs, fp16 output.
// 4 nodes/block, 64 threads/node.
// ---------------------------------------------------------------------------
#define PADR 68

__global__ __launch_bounds__(256) void attn2(const __half* __restrict__ q,
                                             const __half* __restrict__ k,
                                             const __half* __restrict__ v,
                                             __half* __restrict__ ahi) {
    __shared__ float sq[4][NHEADS * PADR];
    __shared__ float sk[4][NHEADS * PADR];
    __shared__ float sv[4][NHEADS * PADR];
    __shared__ float Ss[4][NHEADS * NHEADS];

    const int tid = threadIdx.x;
    const int ln  = tid >> 6;
    const int t   = tid & 63;
    const size_t base = ((size_t)blockIdx.x * 4 + ln) * DDIM;

    // load 8 halves (16B) per array per thread; convert to fp32 smem
    {
        const int i8 = t * 8;           // 0..504
        const int h  = i8 >> 6;
        const int d  = i8 & 63;
        const __half2* qp = (const __half2*)(q + base + i8);
        const __half2* kp = (const __half2*)(k + base + i8);
        const __half2* vp = (const __half2*)(v + base + i8);
#pragma unroll
        for (int j = 0; j < 4; ++j) {
            float2 fq = __half22float2(qp[j]);
            float2 fk = __half22float2(kp[j]);
            float2 fv = __half22float2(vp[j]);
            sq[ln][h * PADR + d + 2 * j]     = fq.x;
            sq[ln][h * PADR + d + 2 * j + 1] = fq.y;
            sk[ln][h * PADR + d + 2 * j]     = fk.x;
            sk[ln][h * PADR + d + 2 * j + 1] = fk.y;
            sv[ln][h * PADR + d + 2 * j]     = fv.x;
            sv[ln][h * PADR + d + 2 * j + 1] = fv.y;
        }
    }
    __syncthreads();

    {
        const float4* qp = (const float4*)&sq[ln][(t >> 3) * PADR];
        const float4* kp = (const float4*)&sk[ln][(t & 7) * PADR];
        float s = 0.0f;
#pragma unroll
        for (int d4 = 0; d4 < 16; ++d4) {
            float4 a = qp[d4], b = kp[d4];
            s = fmaf(a.x, b.x, s);
            s = fmaf(a.y, b.y, s);
            s = fmaf(a.z, b.z, s);
            s = fmaf(a.w, b.w, s);
        }
        Ss[ln][t] = s;
    }
    __syncthreads();

    {
        const int e = t;
        float sval[NHEADS];
#pragma unroll
        for (int hp = 0; hp < NHEADS; ++hp) sval[hp] = sv[ln][hp * PADR + e];
#pragma unroll
        for (int h = 0; h < NHEADS; ++h) {
            float num = 0.0f, den = 0.0f;
#pragma unroll
            for (int hp = 0; hp < NHEADS; ++hp) {
                const float Sv = Ss[ln][h * NHEADS + hp];
                den += Sv;
                num = fmaf(Sv, sval[hp], num);
            }
            ahi[base + h * HDIM + e] = __float2half(num / den);
        }
    }
}

// ---------------------------------------------------------------------------
// Fused residual + LayerNorm, one warp per row, float4 vectorized.
// ---------------------------------------------------------------------------
__global__ __launch_bounds__(256) void ln_kernel(const float* __restrict__ h,
                                                 const float* __restrict__ fh,
                                                 const float* __restrict__ gamma,
                                                 const float* __restrict__ beta,
                                                 float* __restrict__ out) {
    const int row  = (blockIdx.x * blockDim.x + threadIdx.x) >> 5;
    const int lane = threadIdx.x & 31;
    if (row >= NROWS) return;

    const size_t b4 = (size_t)row * 128;   // float4 base
    float4 x[4];
    float s = 0.0f;
#pragma unroll
    for (int i = 0; i < 4; ++i) {
        const int c = lane + i * 32;
        float4 a = ((const float4*)h)[b4 + c];
        float4 f = ((const float4*)fh)[b4 + c];
        x[i].x = a.x + f.x; x[i].y = a.y + f.y;
        x[i].z = a.z + f.z; x[i].w = a.w + f.w;
        s += x[i].x + x[i].y + x[i].z + x[i].w;
    }
#pragma unroll
    for (int off = 16; off > 0; off >>= 1) s += __shfl_xor_sync(0xffffffffu, s, off);
    const float mu = s * (1.0f / DDIM);

    float var = 0.0f;
#pragma unroll
    for (int i = 0; i < 4; ++i) {
        float dx = x[i].x - mu, dy = x[i].y - mu, dz = x[i].z - mu, dw = x[i].w - mu;
        var = fmaf(dx, dx, var); var = fmaf(dy, dy, var);
        var = fmaf(dz, dz, var); var = fmaf(dw, dw, var);
    }
#pragma unroll
    for (int off = 16; off > 0; off >>= 1) var += __shfl_xor_sync(0xffffffffu, var, off);
    var *= (1.0f / DDIM);

    const float r = rsqrtf(var + LN_EPS);
#pragma unroll
    for (int i = 0; i < 4; ++i) {
        const int c = lane + i * 32;
        float4 g = ((const float4*)gamma)[c];
        float4 bt = ((const float4*)beta)[c];
        float4 o;
        o.x = (x[i].x - mu) * r * g.x + bt.x;
        o.y = (x[i].y - mu) * r * g.y + bt.y;
        o.z = (x[i].z - mu) * r * g.z + bt.z;
        o.w = (x[i].w - mu) * r * g.w + bt.w;
        ((float4*)out)[b4 + c] = o;
    }
}

// ---------------------------------------------------------------------------
// kernel_launch
// ---------------------------------------------------------------------------
extern "C" void kernel_launch(void* const* d_in, const int* in_sizes, int n_in,
                              void* d_out, int out_size) {
    const float* h     = (const float*)d_in[0];
    const float* Wq    = (const float*)d_in[1];
    const float* Wk    = (const float*)d_in[2];
    const float* Wv    = (const float*)d_in[3];
    const float* Wf    = (const float*)d_in[4];
    const float* gamma = (const float*)d_in[5];
    const float* beta  = (const float*)d_in[6];

    float* out = (float*)d_out;
    float* q   = out + (size_t)NROWS * DDIM;

    void *hhi, *qkvh, *athi, *wthi, *wtlo, *fhp;
    cudaGetSymbolAddress(&hhi, g_h_hi);
    cudaGetSymbolAddress(&qkvh, g_qkvh);
    cudaGetSymbolAddress(&athi, g_at_hi);
    cudaGetSymbolAddress(&wthi, g_wt_hi);
    cudaGetSymbolAddress(&wtlo, g_wt_lo);
    cudaGetSymbolAddress(&fhp, g_fh);

    cudaFuncSetAttribute(gemm_mma<2, true>,
                         cudaFuncAttributeMaxDynamicSharedMemorySize, SMEM_DYN_QKV);
    cudaFuncSetAttribute(gemm_mma<1, false>,
                         cudaFuncAttributeMaxDynamicSharedMemorySize, SMEM_DYN_WF);

    __half* Hhi  = (__half*)hhi;
    __half* Qkvh = (__half*)qkvh;
    __half* Ath  = (__half*)athi;
    __half* WTh  = (__half*)wthi;
    __half* WTl  = (__half*)wtlo;

    conv_h<<<(NROWS * DDIM) / 4 / 256, 256>>>(h, Hhi);
    conv_wt<<<dim3(16, 16, 4), dim3(32, 8)>>>(Wq, Wk, Wv, Wf, WTh, WTl);

    const size_t WSZ = (size_t)DDIM * DDIM;
    const size_t NDS = (size_t)NROWS * DDIM;

    // fused q,k,v projections (z = 0,1,2); fp32 to out slabs + fp16 to Qkvh
    gemm_mma<2, true><<<dim3(4, 256, 3), 256, SMEM_DYN_QKV>>>(Hhi, WTh, WTl, q, Qkvh);

    attn2<<<NROWS / 4, 256>>>(Qkvh, Qkvh + NDS, Qkvh + 2 * NDS, Ath);

    // Wf GEMM: single-term fp16 x fp16
    gemm_mma<1, false><<<dim3(4, 256, 1), 256, SMEM_DYN_WF>>>(
        Ath, WTh + 3 * WSZ, nullptr, (float*)fhp, nullptr);

    ln_kernel<<<(NROWS * 32) / 256, 256>>>(h, (const float*)fhp, gamma, beta, out);
}

// round 12
// speedup vs baseline: 2.2895x; 1.2976x over previous
#include <cuda_runtime.h>
#include <cuda_fp16.h>
#include <cstdint>

// Problem constants (AGTLayer: N=32768, D=512, H=8, HD=64)
#define NROWS 32768
#define DDIM  512
#define NHEADS 8
#define HDIM  64
#define LN_EPS 1e-5f

// ---------------------------------------------------------------------------
// Scratch (__device__ globals; allocation-free rule)
// ---------------------------------------------------------------------------
__device__ __half g_h_hi[(size_t)NROWS * DDIM];
__device__ __half g_qkvh[3 * (size_t)NROWS * DDIM];  // fp16 copies of q,k,v
__device__ __half g_at_hi[(size_t)NROWS * DDIM];
__device__ __half g_wt_hi[4 * DDIM * DDIM];          // transposed: Wt[n][k]
__device__ float g_fh[(size_t)NROWS * DDIM];

// ---------------------------------------------------------------------------
// helpers
// ---------------------------------------------------------------------------
__device__ __forceinline__ uint32_t s2u(const void* p) {
    uint32_t a;
    asm("{ .reg .u64 t; cvta.to.shared.u64 t, %1; cvt.u32.u64 %0, t; }"
        : "=r"(a) : "l"(p));
    return a;
}

__device__ __forceinline__ void cpasync16(uint32_t dst, const void* src) {
    asm volatile("cp.async.cg.shared.global [%0], [%1], 16;" :: "r"(dst), "l"(src));
}
__device__ __forceinline__ void cp_commit() {
    asm volatile("cp.async.commit_group;" ::: "memory");
}
__device__ __forceinline__ void cp_wait2() {
    asm volatile("cp.async.wait_group 2;" ::: "memory");
}

__device__ __forceinline__ void ldm_x4(uint32_t* r, uint32_t addr) {
    asm volatile("ldmatrix.sync.aligned.m8n8.x4.shared.b16 {%0,%1,%2,%3}, [%4];"
                 : "=r"(r[0]), "=r"(r[1]), "=r"(r[2]), "=r"(r[3]) : "r"(addr));
}

__device__ __forceinline__ void mma16816(float* c, const uint32_t* a, const uint32_t* b) {
    asm volatile(
        "mma.sync.aligned.m16n8k16.row.col.f32.f16.f16.f32 "
        "{%0,%1,%2,%3}, {%4,%5,%6,%7}, {%8,%9}, {%0,%1,%2,%3};"
        : "+f"(c[0]), "+f"(c[1]), "+f"(c[2]), "+f"(c[3])
        : "r"(a[0]), "r"(a[1]), "r"(a[2]), "r"(a[3]), "r"(b[0]), "r"(b[1]));
}

// swizzled smem byte offset within a tile: rows of 64 B (32 halves), 4 16B segs
__device__ __forceinline__ uint32_t swz(int row, int seg) {
    return (uint32_t)(row * 64 + ((seg ^ ((row >> 1) & 3)) << 4));
}

// ---------------------------------------------------------------------------
// Conversion: h fp32 -> fp16
// ---------------------------------------------------------------------------
__global__ __launch_bounds__(256) void conv_h(const float* __restrict__ src,
                                              __half* __restrict__ hi) {
    const size_t i4 = (size_t)blockIdx.x * 256 + threadIdx.x;
    float4 x = ((const float4*)src)[i4];
    __half2 h01, h23;
    h01.x = __float2half(x.x); h01.y = __float2half(x.y);
    h23.x = __float2half(x.z); h23.y = __float2half(x.w);
    ((__half2*)hi)[i4 * 2]     = h01;
    ((__half2*)hi)[i4 * 2 + 1] = h23;
}

// ---------------------------------------------------------------------------
// Conversion + transpose: W[k][n] fp32 -> Wt[n][k] fp16 (4 matrices)
// ---------------------------------------------------------------------------
__global__ __launch_bounds__(256) void conv_wt(const float* __restrict__ W0,
                                               const float* __restrict__ W1,
                                               const float* __restrict__ W2,
                                               const float* __restrict__ W3,
                                               __half* __restrict__ hi) {
    const float* W = (blockIdx.z == 0) ? W0 : (blockIdx.z == 1) ? W1
                     : (blockIdx.z == 2) ? W2 : W3;
    __shared__ float t[32][33];
    const int tx = threadIdx.x, ty = threadIdx.y;  // 32 x 8
    const int n0 = blockIdx.x * 32, k0 = blockIdx.y * 32;
#pragma unroll
    for (int i = 0; i < 4; ++i)
        t[ty + i * 8][tx] = W[(size_t)(k0 + ty + i * 8) * DDIM + n0 + tx];
    __syncthreads();
    const size_t base = (size_t)blockIdx.z * DDIM * DDIM;
#pragma unroll
    for (int i = 0; i < 4; ++i) {
        const int n = n0 + ty + i * 8;
        const int k = k0 + tx;
        hi[base + (size_t)n * DDIM + k] = __float2half(t[tx][ty + i * 8]);
    }
}

// ---------------------------------------------------------------------------
// HMMA fp16 GEMM: C[M,512] fp32 = A @ Wt^T  (single term, fp32 accum)
// CTA 128x128, BK=32, 8 warps (64x32), 4-stage cp.async, swizzled + ldmatrix.
// QKV=true: gridDim.z selects weight/output slab; relu for z<2; also emits
// fp16 copy of C to Ch (for the attention kernel).
// ---------------------------------------------------------------------------
#define TILE_B   (128 * 64)              // 8192 B per operand tile
#define NSTAGE   4
#define STAGE_B  (2 * TILE_B)            // Ah, Bh = 16384 B
#define SMEM_DYN 69632                   // stages 65536; epilogue Csh 67584

template <bool QKV>
__global__ __launch_bounds__(256) void gemm_mma(const __half* __restrict__ Ah,
                                                const __half* __restrict__ Bh0,
                                                float* __restrict__ C0,
                                                __half* __restrict__ Ch0) {
    extern __shared__ char dsm[];
    const uint32_t sb = s2u(dsm);

    const int tid  = threadIdx.x;
    const int wid  = tid >> 5;
    const int lane = tid & 31;
    const int bm   = blockIdx.y * 128;
    const int bn   = blockIdx.x * 128;

    const size_t zoffW = QKV ? (size_t)blockIdx.z * DDIM * DDIM : 0;
    const size_t zoffC = QKV ? (size_t)blockIdx.z * NROWS * DDIM : 0;
    const __half* Bh = Bh0 + zoffW;
    float* C = C0 + zoffC;
    __half* Ch = QKV ? (Ch0 + zoffC) : nullptr;
    const bool relu = QKV ? (blockIdx.z < 2) : false;

    const int wm = (wid & 1) * 64;   // warp m offset
    const int wn = (wid >> 1) * 32;  // warp n offset

    float acc[4][4][4];
#pragma unroll
    for (int i = 0; i < 4; ++i)
#pragma unroll
        for (int j = 0; j < 4; ++j)
#pragma unroll
            for (int r = 0; r < 4; ++r) acc[i][j][r] = 0.0f;

    auto load_stage = [&](int stage, int kc) {
        const uint32_t s0 = sb + stage * STAGE_B;
#pragma unroll
        for (int it = 0; it < 2; ++it) {
            const int ch  = tid + it * 256;     // 0..511
            const int row = ch >> 2;
            const int seg = ch & 3;
            cpasync16(s0 + swz(row, seg),
                      Ah + (size_t)(bm + row) * DDIM + kc + seg * 8);
            cpasync16(s0 + TILE_B + swz(row, seg),
                      Bh + (size_t)(bn + row) * DDIM + kc + seg * 8);
        }
    };

    // prologue: stages 0,1,2
#pragma unroll
    for (int s = 0; s < 3; ++s) {
        load_stage(s, s * 32);
        cp_commit();
    }

    // ldmatrix lane roles
    const int a_row = lane & 15;
    const int a_sg  = lane >> 4;
    const int b_row = ((lane >> 4) & 1) * 8 + (lane & 7);
    const int b_sg  = (lane >> 3) & 1;

    for (int kt = 0; kt < 16; ++kt) {
        cp_wait2();          // stage kt resident
        __syncthreads();     // stage (kt+3)%4 free

        if (kt + 3 < 16) load_stage((kt + 3) & (NSTAGE - 1), (kt + 3) * 32);
        cp_commit();

        const uint32_t s0  = sb + (kt & (NSTAGE - 1)) * STAGE_B;
        const uint32_t aho = s0;
        const uint32_t bho = s0 + TILE_B;

#pragma unroll
        for (int s = 0; s < 2; ++s) {
            const int ksg = s * 2;
            uint32_t bh[4][2];
#pragma unroll
            for (int jp = 0; jp < 2; ++jp) {
                const uint32_t ba = swz(wn + jp * 16 + b_row, ksg + b_sg);
                uint32_t r[4];
                ldm_x4(r, bho + ba);
                bh[jp * 2][0] = r[0]; bh[jp * 2][1] = r[1];
                bh[jp * 2 + 1][0] = r[2]; bh[jp * 2 + 1][1] = r[3];
            }
#pragma unroll
            for (int i = 0; i < 4; ++i) {
                const uint32_t aa = swz(wm + i * 16 + a_row, ksg + a_sg);
                uint32_t ah[4];
                ldm_x4(ah, aho + aa);
#pragma unroll
                for (int j = 0; j < 4; ++j) mma16816(acc[i][j], ah, bh[j]);
            }
        }
    }

    __syncthreads();

    // epilogue: acc -> padded smem -> coalesced stores (fp32 + optional fp16)
    const int r4 = lane >> 2;
    const int c2 = (lane & 3) * 2;
    float* Csh = (float*)dsm;   // 128 x 132 floats = 67584 B
#pragma unroll
    for (int i = 0; i < 4; ++i) {
#pragma unroll
        for (int j = 0; j < 4; ++j) {
            const int row = wm + i * 16 + r4;
            const int col = wn + j * 8 + c2;
            float d0 = acc[i][j][0], d1 = acc[i][j][1];
            float d2 = acc[i][j][2], d3 = acc[i][j][3];
            if (relu) {
                d0 = fmaxf(d0, 0.0f); d1 = fmaxf(d1, 0.0f);
                d2 = fmaxf(d2, 0.0f); d3 = fmaxf(d3, 0.0f);
            }
            *(float2*)&Csh[row * 132 + col]       = make_float2(d0, d1);
            *(float2*)&Csh[(row + 8) * 132 + col] = make_float2(d2, d3);
        }
    }
    __syncthreads();

#pragma unroll
    for (int i = 0; i < 16; ++i) {
        const int idx = tid + i * 256;   // float4 id, 0..4095
        const int r   = idx >> 5;
        const int c4  = (idx & 31) * 4;
        const float* cr = Csh + r * 132 + c4;
        float4 v4 = make_float4(cr[0], cr[1], cr[2], cr[3]);
        *(float4*)(C + (size_t)(bm + r) * DDIM + bn + c4) = v4;
        if (QKV) {
            __half2 p0, p1;
            p0.x = __float2half(v4.x); p0.y = __float2half(v4.y);
            p1.x = __float2half(v4.z); p1.y = __float2half(v4.w);
            __half2* cp = (__half2*)(Ch + (size_t)(bm + r) * DDIM + bn + c4);
            cp[0] = p0;
            cp[1] = p1;
        }
    }
}

// ---------------------------------------------------------------------------
// Per-node linear attention via 8x8 score matrix, fp16 inputs.
// q,k in fp16 smem (dot phase, fp32 accumulate); v in fp32 smem (output).
// 4 nodes/block, 64 threads/node.
// ---------------------------------------------------------------------------
#define PADH 72   // halves per head row for q,k (144 B)
#define PADR 68   // floats per head row for v

__global__ __launch_bounds__(256) void attn2(const __half* __restrict__ q,
                                             const __half* __restrict__ k,
                                             const __half* __restrict__ v,
                                             __half* __restrict__ ahi) {
    __shared__ __half hq[4][NHEADS * PADH];
    __shared__ __half hk[4][NHEADS * PADH];
    __shared__ float  sv[4][NHEADS * PADR];
    __shared__ float  Ss[4][NHEADS * NHEADS];

    const int tid = threadIdx.x;
    const int ln  = tid >> 6;
    const int t   = tid & 63;
    const size_t base = ((size_t)blockIdx.x * 4 + ln) * DDIM;

    {
        const int i8 = t * 8;           // 0..504
        const int h  = i8 >> 6;
        const int d  = i8 & 63;
        // q,k: 16B fp16 copy
        *(uint4*)&hq[ln][h * PADH + d] = *(const uint4*)(q + base + i8);
        *(uint4*)&hk[ln][h * PADH + d] = *(const uint4*)(k + base + i8);
        // v: convert to fp32
        const __half2* vp = (const __half2*)(v + base + i8);
#pragma unroll
        for (int j = 0; j < 4; ++j) {
            float2 fv = __half22float2(vp[j]);
            sv[ln][h * PADR + d + 2 * j]     = fv.x;
            sv[ln][h * PADR + d + 2 * j + 1] = fv.y;
        }
    }
    __syncthreads();

    {
        const uint4* qp = (const uint4*)&hq[ln][(t >> 3) * PADH];
        const uint4* kp = (const uint4*)&hk[ln][(t & 7) * PADH];
        float s = 0.0f;
#pragma unroll
        for (int c = 0; c < 8; ++c) {
            uint4 a = qp[c], b = kp[c];
            const __half2* ah = (const __half2*)&a;
            const __half2* bh = (const __half2*)&b;
#pragma unroll
            for (int j = 0; j < 4; ++j) {
                float2 fa = __half22float2(ah[j]);
                float2 fb = __half22float2(bh[j]);
                s = fmaf(fa.x, fb.x, s);
                s = fmaf(fa.y, fb.y, s);
            }
        }
        Ss[ln][t] = s;
    }
    __syncthreads();

    {
        const int e = t;
        float sval[NHEADS];
#pragma unroll
        for (int hp = 0; hp < NHEADS; ++hp) sval[hp] = sv[ln][hp * PADR + e];
#pragma unroll
        for (int h = 0; h < NHEADS; ++h) {
            float num = 0.0f, den = 0.0f;
#pragma unroll
            for (int hp = 0; hp < NHEADS; ++hp) {
                const float Sv = Ss[ln][h * NHEADS + hp];
                den += Sv;
                num = fmaf(Sv, sval[hp], num);
            }
            ahi[base + h * HDIM + e] = __float2half(num / den);
        }
    }
}

// ---------------------------------------------------------------------------
// Fused residual + LayerNorm, one warp per row, float4 vectorized.
// ---------------------------------------------------------------------------
__global__ __launch_bounds__(256) void ln_kernel(const float* __restrict__ h,
                                                 const float* __restrict__ fh,
                                                 const float* __restrict__ gamma,
                                                 const float* __restrict__ beta,
                                                 float* __restrict__ out) {
    const int row  = (blockIdx.x * blockDim.x + threadIdx.x) >> 5;
    const int lane = threadIdx.x & 31;
    if (row >= NROWS) return;

    const size_t b4 = (size_t)row * 128;   // float4 base
    float4 x[4];
    float s = 0.0f;
#pragma unroll
    for (int i = 0; i < 4; ++i) {
        const int c = lane + i * 32;
        float4 a = ((const float4*)h)[b4 + c];
        float4 f = ((const float4*)fh)[b4 + c];
        x[i].x = a.x + f.x; x[i].y = a.y + f.y;
        x[i].z = a.z + f.z; x[i].w = a.w + f.w;
        s += x[i].x + x[i].y + x[i].z + x[i].w;
    }
#pragma unroll
    for (int off = 16; off > 0; off >>= 1) s += __shfl_xor_sync(0xffffffffu, s, off);
    const float mu = s * (1.0f / DDIM);

    float var = 0.0f;
#pragma unroll
    for (int i = 0; i < 4; ++i) {
        float dx = x[i].x - mu, dy = x[i].y - mu, dz = x[i].z - mu, dw = x[i].w - mu;
        var = fmaf(dx, dx, var); var = fmaf(dy, dy, var);
        var = fmaf(dz, dz, var); var = fmaf(dw, dw, var);
    }
#pragma unroll
    for (int off = 16; off > 0; off >>= 1) var += __shfl_xor_sync(0xffffffffu, var, off);
    var *= (1.0f / DDIM);

    const float r = rsqrtf(var + LN_EPS);
#pragma unroll
    for (int i = 0; i < 4; ++i) {
        const int c = lane + i * 32;
        float4 g = ((const float4*)gamma)[c];
        float4 bt = ((const float4*)beta)[c];
        float4 o;
        o.x = (x[i].x - mu) * r * g.x + bt.x;
        o.y = (x[i].y - mu) * r * g.y + bt.y;
        o.z = (x[i].z - mu) * r * g.z + bt.z;
        o.w = (x[i].w - mu) * r * g.w + bt.w;
        ((float4*)out)[b4 + c] = o;
    }
}

// ---------------------------------------------------------------------------
// kernel_launch
// ---------------------------------------------------------------------------
extern "C" void kernel_launch(void* const* d_in, const int* in_sizes, int n_in,
                              void* d_out, int out_size) {
    const float* h     = (const float*)d_in[0];
    const float* Wq    = (const float*)d_in[1];
    const float* Wk    = (const float*)d_in[2];
    const float* Wv    = (const float*)d_in[3];
    const float* Wf    = (const float*)d_in[4];
    const float* gamma = (const float*)d_in[5];
    const float* beta  = (const float*)d_in[6];

    float* out = (float*)d_out;
    float* q   = out + (size_t)NROWS * DDIM;

    void *hhi, *qkvh, *athi, *wthi, *fhp;
    cudaGetSymbolAddress(&hhi, g_h_hi);
    cudaGetSymbolAddress(&qkvh, g_qkvh);
    cudaGetSymbolAddress(&athi, g_at_hi);
    cudaGetSymbolAddress(&wthi, g_wt_hi);
    cudaGetSymbolAddress(&fhp, g_fh);

    cudaFuncSetAttribute(gemm_mma<true>,
                         cudaFuncAttributeMaxDynamicSharedMemorySize, SMEM_DYN);
    cudaFuncSetAttribute(gemm_mma<false>,
                         cudaFuncAttributeMaxDynamicSharedMemorySize, SMEM_DYN);

    __half* Hhi  = (__half*)hhi;
    __half* Qkvh = (__half*)qkvh;
    __half* Ath  = (__half*)athi;
    __half* WTh  = (__half*)wthi;

    conv_h<<<(NROWS * DDIM) / 4 / 256, 256>>>(h, Hhi);
    conv_wt<<<dim3(16, 16, 4), dim3(32, 8)>>>(Wq, Wk, Wv, Wf, WTh);

    const size_t WSZ = (size_t)DDIM * DDIM;
    const size_t NDS = (size_t)NROWS * DDIM;

    // fused q,k,v projections (z = 0,1,2); fp32 to out slabs + fp16 to Qkvh
    gemm_mma<true><<<dim3(4, 256, 3), 256, SMEM_DYN>>>(Hhi, WTh, q, Qkvh);

    attn2<<<NROWS / 4, 256>>>(Qkvh, Qkvh + NDS, Qkvh + 2 * NDS, Ath);

    // Wf GEMM: fp16 x fp16
    gemm_mma<false><<<dim3(4, 256, 1), 256, SMEM_DYN>>>(
        Ath, WTh + 3 * WSZ, (float*)fhp, nullptr);

    ln_kernel<<<(NROWS * 32) / 256, 256>>>(h, (const float*)fhp, gamma, beta, out);
}

// round 13
// speedup vs baseline: 2.5413x; 1.1100x over previous
#include <cuda_runtime.h>
#include <cuda_fp16.h>
#include <cstdint>

// Problem constants (AGTLayer: N=32768, D=512, H=8, HD=64)
#define NROWS 32768
#define DDIM  512
#define NHEADS 8
#define HDIM  64
#define LN_EPS 1e-5f

// ---------------------------------------------------------------------------
// Scratch (__device__ globals; allocation-free rule)
// ---------------------------------------------------------------------------
__device__ __half g_h_hi[(size_t)NROWS * DDIM];
__device__ __half g_qkvh[3 * (size_t)NROWS * DDIM];  // fp16 copies of q,k,v
__device__ __half g_at_hi[(size_t)NROWS * DDIM];
__device__ __half g_wt_hi[4 * DDIM * DDIM];          // transposed: Wt[n][k]
__device__ __half g_fh[(size_t)NROWS * DDIM];        // fh in fp16

// ---------------------------------------------------------------------------
// helpers
// ---------------------------------------------------------------------------
__device__ __forceinline__ uint32_t s2u(const void* p) {
    uint32_t a;
    asm("{ .reg .u64 t; cvta.to.shared.u64 t, %1; cvt.u32.u64 %0, t; }"
        : "=r"(a) : "l"(p));
    return a;
}

__device__ __forceinline__ void cpasync16(uint32_t dst, const void* src) {
    asm volatile("cp.async.cg.shared.global [%0], [%1], 16;" :: "r"(dst), "l"(src));
}
__device__ __forceinline__ void cp_commit() {
    asm volatile("cp.async.commit_group;" ::: "memory");
}
__device__ __forceinline__ void cp_wait1() {
    asm volatile("cp.async.wait_group 1;" ::: "memory");
}

__device__ __forceinline__ void ldm_x4(uint32_t* r, uint32_t addr) {
    asm volatile("ldmatrix.sync.aligned.m8n8.x4.shared.b16 {%0,%1,%2,%3}, [%4];"
                 : "=r"(r[0]), "=r"(r[1]), "=r"(r[2]), "=r"(r[3]) : "r"(addr));
}

__device__ __forceinline__ void mma16816(float* c, const uint32_t* a, const uint32_t* b) {
    asm volatile(
        "mma.sync.aligned.m16n8k16.row.col.f32.f16.f16.f32 "
        "{%0,%1,%2,%3}, {%4,%5,%6,%7}, {%8,%9}, {%0,%1,%2,%3};"
        : "+f"(c[0]), "+f"(c[1]), "+f"(c[2]), "+f"(c[3])
        : "r"(a[0]), "r"(a[1]), "r"(a[2]), "r"(a[3]), "r"(b[0]), "r"(b[1]));
}

// SW128 swizzle for 128B rows (64 halves): seg(0..7) XOR low row bits
__device__ __forceinline__ uint32_t swz128(int row, int seg) {
    return (uint32_t)(row * 128 + ((seg ^ (row & 7)) << 4));
}

// ---------------------------------------------------------------------------
// Conversion: h fp32 -> fp16
// ---------------------------------------------------------------------------
__global__ __launch_bounds__(256) void conv_h(const float* __restrict__ src,
                                              __half* __restrict__ hi) {
    const size_t i4 = (size_t)blockIdx.x * 256 + threadIdx.x;
    float4 x = ((const float4*)src)[i4];
    __half2 h01, h23;
    h01.x = __float2half(x.x); h01.y = __float2half(x.y);
    h23.x = __float2half(x.z); h23.y = __float2half(x.w);
    ((__half2*)hi)[i4 * 2]     = h01;
    ((__half2*)hi)[i4 * 2 + 1] = h23;
}

// ---------------------------------------------------------------------------
// Conversion + transpose: W[k][n] fp32 -> Wt[n][k] fp16 (4 matrices)
// ---------------------------------------------------------------------------
__global__ __launch_bounds__(256) void conv_wt(const float* __restrict__ W0,
                                               const float* __restrict__ W1,
                                               const float* __restrict__ W2,
                                               const float* __restrict__ W3,
                                               __half* __restrict__ hi) {
    const float* W = (blockIdx.z == 0) ? W0 : (blockIdx.z == 1) ? W1
                     : (blockIdx.z == 2) ? W2 : W3;
    __shared__ float t[32][33];
    const int tx = threadIdx.x, ty = threadIdx.y;  // 32 x 8
    const int n0 = blockIdx.x * 32, k0 = blockIdx.y * 32;
#pragma unroll
    for (int i = 0; i < 4; ++i)
        t[ty + i * 8][tx] = W[(size_t)(k0 + ty + i * 8) * DDIM + n0 + tx];
    __syncthreads();
    const size_t base = (size_t)blockIdx.z * DDIM * DDIM;
#pragma unroll
    for (int i = 0; i < 4; ++i) {
        const int n = n0 + ty + i * 8;
        const int k = k0 + tx;
        hi[base + (size_t)n * DDIM + k] = __float2half(t[tx][ty + i * 8]);
    }
}

// ---------------------------------------------------------------------------
// HMMA fp16 GEMM: C fp32 (or fp16) = A @ Wt^T, fp32 accum.
// CTA 128x128, BK=64, 8 warps (64x32), 3-stage cp.async, SW128 + ldmatrix.
// QKV=true: gridDim.z selects weight/output slab; relu for z<2; fp32 C to
// out slabs + fp16 copy to Ch. QKV=false: fp16 C only (fh).
// ---------------------------------------------------------------------------
#define TILE_B   (128 * 128)             // 16384 B per operand tile (BK=64)
#define NSTAGE   3
#define STAGE_B  (2 * TILE_B)            // Ah, Bh = 32768 B
#define SMEM_DYN (NSTAGE * STAGE_B)      // 98304 B; epilogue Csh 67584 fits

template <bool QKV>
__global__ __launch_bounds__(256) void gemm_mma(const __half* __restrict__ Ah,
                                                const __half* __restrict__ Bh0,
                                                float* __restrict__ C0,
                                                __half* __restrict__ Ch0) {
    extern __shared__ char dsm[];
    const uint32_t sb = s2u(dsm);

    const int tid  = threadIdx.x;
    const int wid  = tid >> 5;
    const int lane = tid & 31;
    const int bm   = blockIdx.y * 128;
    const int bn   = blockIdx.x * 128;

    const size_t zoffW = QKV ? (size_t)blockIdx.z * DDIM * DDIM : 0;
    const size_t zoffC = QKV ? (size_t)blockIdx.z * NROWS * DDIM : 0;
    const __half* Bh = Bh0 + zoffW;
    float* C = QKV ? (C0 + zoffC) : nullptr;
    __half* Ch = Ch0 + zoffC;
    const bool relu = QKV ? (blockIdx.z < 2) : false;

    const int wm = (wid & 1) * 64;   // warp m offset
    const int wn = (wid >> 1) * 32;  // warp n offset

    float acc[4][4][4];
#pragma unroll
    for (int i = 0; i < 4; ++i)
#pragma unroll
        for (int j = 0; j < 4; ++j)
#pragma unroll
            for (int r = 0; r < 4; ++r) acc[i][j][r] = 0.0f;

    // stage loader: 2 tiles x 128 rows x 8 segs = 2048 chunks, 8 per thread
    auto load_stage = [&](int stage, int kc) {
        const uint32_t s0 = sb + stage * STAGE_B;
#pragma unroll
        for (int it = 0; it < 4; ++it) {
            const int ch  = tid + it * 256;     // 0..1023
            const int row = ch >> 3;
            const int seg = ch & 7;
            cpasync16(s0 + swz128(row, seg),
                      Ah + (size_t)(bm + row) * DDIM + kc + seg * 8);
            cpasync16(s0 + TILE_B + swz128(row, seg),
                      Bh + (size_t)(bn + row) * DDIM + kc + seg * 8);
        }
    };

    // prologue: stages 0,1
    load_stage(0, 0);
    cp_commit();
    load_stage(1, 64);
    cp_commit();

    // ldmatrix lane roles
    const int a_row = lane & 15;
    const int a_sg  = lane >> 4;                 // 16B within k16 (0/1)
    const int b_row = ((lane >> 4) & 1) * 8 + (lane & 7);
    const int b_sg  = (lane >> 3) & 1;

    for (int kt = 0; kt < 8; ++kt) {
        cp_wait1();          // stage kt resident
        __syncthreads();     // stage (kt+2)%3 free

        if (kt + 2 < 8) load_stage((kt + 2) % NSTAGE, (kt + 2) * 64);
        cp_commit();

        const uint32_t s0  = sb + (kt % NSTAGE) * STAGE_B;
        const uint32_t aho = s0;
        const uint32_t bho = s0 + TILE_B;

#pragma unroll
        for (int s = 0; s < 4; ++s) {
            const int ksg = s * 2;               // 16B-seg base of this k16
            uint32_t bh[4][2];
#pragma unroll
            for (int jp = 0; jp < 2; ++jp) {
                const uint32_t ba = swz128(wn + jp * 16 + b_row, ksg + b_sg);
                uint32_t r[4];
                ldm_x4(r, bho + ba);
                bh[jp * 2][0] = r[0]; bh[jp * 2][1] = r[1];
                bh[jp * 2 + 1][0] = r[2]; bh[jp * 2 + 1][1] = r[3];
            }
#pragma unroll
            for (int i = 0; i < 4; ++i) {
                const uint32_t aa = swz128(wm + i * 16 + a_row, ksg + a_sg);
                uint32_t ah[4];
                ldm_x4(ah, aho + aa);
#pragma unroll
                for (int j = 0; j < 4; ++j) mma16816(acc[i][j], ah, bh[j]);
            }
        }
    }

    __syncthreads();

    // epilogue: acc -> padded smem -> coalesced stores
    const int r4 = lane >> 2;
    const int c2 = (lane & 3) * 2;
    float* Csh = (float*)dsm;   // 128 x 132 floats = 67584 B
#pragma unroll
    for (int i = 0; i < 4; ++i) {
#pragma unroll
        for (int j = 0; j < 4; ++j) {
            const int row = wm + i * 16 + r4;
            const int col = wn + j * 8 + c2;
            float d0 = acc[i][j][0], d1 = acc[i][j][1];
            float d2 = acc[i][j][2], d3 = acc[i][j][3];
            if (relu) {
                d0 = fmaxf(d0, 0.0f); d1 = fmaxf(d1, 0.0f);
                d2 = fmaxf(d2, 0.0f); d3 = fmaxf(d3, 0.0f);
            }
            *(float2*)&Csh[row * 132 + col]       = make_float2(d0, d1);
            *(float2*)&Csh[(row + 8) * 132 + col] = make_float2(d2, d3);
        }
    }
    __syncthreads();

#pragma unroll
    for (int i = 0; i < 16; ++i) {
        const int idx = tid + i * 256;   // float4 id, 0..4095
        const int r   = idx >> 5;
        const int c4  = (idx & 31) * 4;
        const float* cr = Csh + r * 132 + c4;
        float4 v4 = make_float4(cr[0], cr[1], cr[2], cr[3]);
        __half2 p0, p1;
        p0.x = __float2half(v4.x); p0.y = __float2half(v4.y);
        p1.x = __float2half(v4.z); p1.y = __float2half(v4.w);
        if (QKV)
            *(float4*)(C + (size_t)(bm + r) * DDIM + bn + c4) = v4;
        __half2* cp = (__half2*)(Ch + (size_t)(bm + r) * DDIM + bn + c4);
        cp[0] = p0;
        cp[1] = p1;
    }
}

// ---------------------------------------------------------------------------
// Per-node linear attention via 8x8 score matrix, fp16 inputs.
// ---------------------------------------------------------------------------
#define PADH 72   // halves per head row for q,k
#define PADR 68   // floats per head row for v

__global__ __launch_bounds__(256) void attn2(const __half* __restrict__ q,
                                             const __half* __restrict__ k,
                                             const __half* __restrict__ v,
                                             __half* __restrict__ ahi) {
    __shared__ __half hq[4][NHEADS * PADH];
    __shared__ __half hk[4][NHEADS * PADH];
    __shared__ float  sv[4][NHEADS * PADR];
    __shared__ float  Ss[4][NHEADS * NHEADS];

    const int tid = threadIdx.x;
    const int ln  = tid >> 6;
    const int t   = tid & 63;
    const size_t base = ((size_t)blockIdx.x * 4 + ln) * DDIM;

    {
        const int i8 = t * 8;           // 0..504
        const int h  = i8 >> 6;
        const int d  = i8 & 63;
        *(uint4*)&hq[ln][h * PADH + d] = *(const uint4*)(q + base + i8);
        *(uint4*)&hk[ln][h * PADH + d] = *(const uint4*)(k + base + i8);
        const __half2* vp = (const __half2*)(v + base + i8);
#pragma unroll
        for (int j = 0; j < 4; ++j) {
            float2 fv = __half22float2(vp[j]);
            sv[ln][h * PADR + d + 2 * j]     = fv.x;
            sv[ln][h * PADR + d + 2 * j + 1] = fv.y;
        }
    }
    __syncthreads();

    {
        const uint4* qp = (const uint4*)&hq[ln][(t >> 3) * PADH];
        const uint4* kp = (const uint4*)&hk[ln][(t & 7) * PADH];
        float s = 0.0f;
#pragma unroll
        for (int c = 0; c < 8; ++c) {
            uint4 a = qp[c], b = kp[c];
            const __half2* ah = (const __half2*)&a;
            const __half2* bh = (const __half2*)&b;
#pragma unroll
            for (int j = 0; j < 4; ++j) {
                float2 fa = __half22float2(ah[j]);
                float2 fb = __half22float2(bh[j]);
                s = fmaf(fa.x, fb.x, s);
                s = fmaf(fa.y, fb.y, s);
            }
        }
        Ss[ln][t] = s;
    }
    __syncthreads();

    {
        const int e = t;
        float sval[NHEADS];
#pragma unroll
        for (int hp = 0; hp < NHEADS; ++hp) sval[hp] = sv[ln][hp * PADR + e];
#pragma unroll
        for (int h = 0; h < NHEADS; ++h) {
            float num = 0.0f, den = 0.0f;
#pragma unroll
            for (int hp = 0; hp < NHEADS; ++hp) {
                const float Sv = Ss[ln][h * NHEADS + hp];
                den += Sv;
                num = fmaf(Sv, sval[hp], num);
            }
            ahi[base + h * HDIM + e] = __float2half(__fdividef(num, den));
        }
    }
}

// ---------------------------------------------------------------------------
// Fused residual + LayerNorm, one warp per row. fh read as fp16.
// ---------------------------------------------------------------------------
__global__ __launch_bounds__(256) void ln_kernel(const float* __restrict__ h,
                                                 const __half* __restrict__ fh,
                                                 const float* __restrict__ gamma,
                                                 const float* __restrict__ beta,
                                                 float* __restrict__ out) {
    const int row  = (blockIdx.x * blockDim.x + threadIdx.x) >> 5;
    const int lane = threadIdx.x & 31;
    if (row >= NROWS) return;

    const size_t b4 = (size_t)row * 128;   // float4 base
    const size_t b8h = (size_t)row * 256;  // half2 base (512 halves / 2)
    float4 x[4];
    float s = 0.0f;
#pragma unroll
    for (int i = 0; i < 4; ++i) {
        const int c = lane + i * 32;
        float4 a = ((const float4*)h)[b4 + c];
        const __half2* fp = ((const __half2*)fh) + b8h + c * 2;
        float2 f0 = __half22float2(fp[0]);
        float2 f1 = __half22float2(fp[1]);
        x[i].x = a.x + f0.x; x[i].y = a.y + f0.y;
        x[i].z = a.z + f1.x; x[i].w = a.w + f1.y;
        s += x[i].x + x[i].y + x[i].z + x[i].w;
    }
#pragma unroll
    for (int off = 16; off > 0; off >>= 1) s += __shfl_xor_sync(0xffffffffu, s, off);
    const float mu = s * (1.0f / DDIM);

    float var = 0.0f;
#pragma unroll
    for (int i = 0; i < 4; ++i) {
        float dx = x[i].x - mu, dy = x[i].y - mu, dz = x[i].z - mu, dw = x[i].w - mu;
        var = fmaf(dx, dx, var); var = fmaf(dy, dy, var);
        var = fmaf(dz, dz, var); var = fmaf(dw, dw, var);
    }
#pragma unroll
    for (int off = 16; off > 0; off >>= 1) var += __shfl_xor_sync(0xffffffffu, var, off);
    var *= (1.0f / DDIM);

    const float r = rsqrtf(var + LN_EPS);
#pragma unroll
    for (int i = 0; i < 4; ++i) {
        const int c = lane + i * 32;
        float4 g = ((const float4*)gamma)[c];
        float4 bt = ((const float4*)beta)[c];
        float4 o;
        o.x = (x[i].x - mu) * r * g.x + bt.x;
        o.y = (x[i].y - mu) * r * g.y + bt.y;
        o.z = (x[i].z - mu) * r * g.z + bt.z;
        o.w = (x[i].w - mu) * r * g.w + bt.w;
        ((float4*)out)[b4 + c] = o;
    }
}

// ---------------------------------------------------------------------------
// kernel_launch
// ---------------------------------------------------------------------------
extern "C" void kernel_launch(void* const* d_in, const int* in_sizes, int n_in,
                              void* d_out, int out_size) {
    const float* h     = (const float*)d_in[0];
    const float* Wq    = (const float*)d_in[1];
    const float* Wk    = (const float*)d_in[2];
    const float* Wv    = (const float*)d_in[3];
    const float* Wf    = (const float*)d_in[4];
    const float* gamma = (const float*)d_in[5];
    const float* beta  = (const float*)d_in[6];

    float* out = (float*)d_out;
    float* q   = out + (size_t)NROWS * DDIM;

    void *hhi, *qkvh, *athi, *wthi, *fhp;
    cudaGetSymbolAddress(&hhi, g_h_hi);
    cudaGetSymbolAddress(&qkvh, g_qkvh);
    cudaGetSymbolAddress(&athi, g_at_hi);
    cudaGetSymbolAddress(&wthi, g_wt_hi);
    cudaGetSymbolAddress(&fhp, g_fh);

    cudaFuncSetAttribute(gemm_mma<true>,
                         cudaFuncAttributeMaxDynamicSharedMemorySize, SMEM_DYN);
    cudaFuncSetAttribute(gemm_mma<false>,
                         cudaFuncAttributeMaxDynamicSharedMemorySize, SMEM_DYN);

    __half* Hhi  = (__half*)hhi;
    __half* Qkvh = (__half*)qkvh;
    __half* Ath  = (__half*)athi;
    __half* WTh  = (__half*)wthi;
    __half* Fh   = (__half*)fhp;

    conv_h<<<(NROWS * DDIM) / 4 / 256, 256>>>(h, Hhi);
    conv_wt<<<dim3(16, 16, 4), dim3(32, 8)>>>(Wq, Wk, Wv, Wf, WTh);

    const size_t WSZ = (size_t)DDIM * DDIM;
    const size_t NDS = (size_t)NROWS * DDIM;

    // fused q,k,v projections (z = 0,1,2); fp32 to out slabs + fp16 to Qkvh
    gemm_mma<true><<<dim3(4, 256, 3), 256, SMEM_DYN>>>(Hhi, WTh, q, Qkvh);

    attn2<<<NROWS / 4, 256>>>(Qkvh, Qkvh + NDS, Qkvh + 2 * NDS, Ath);

    // Wf GEMM: fp16 x fp16 -> fp16 fh
    gemm_mma<false><<<dim3(4, 256, 1), 256, SMEM_DYN>>>(
        Ath, WTh + 3 * WSZ, nullptr, Fh);

    ln_kernel<<<(NROWS * 32) / 256, 256>>>(h, Fh, gamma, beta, out);
}

// round 14
// speedup vs baseline: 2.5539x; 1.0049x over previous
#include <cuda_runtime.h>
#include <cuda_fp16.h>
#include <cstdint>

// Problem constants (AGTLayer: N=32768, D=512, H=8, HD=64)
#define NROWS 32768
#define DDIM  512
#define NHEADS 8
#define HDIM  64
#define LN_EPS 1e-5f

// ---------------------------------------------------------------------------
// Scratch (__device__ globals; allocation-free rule)
// ---------------------------------------------------------------------------
__device__ __half g_h_hi[(size_t)NROWS * DDIM];
__device__ __half g_qkvh[3 * (size_t)NROWS * DDIM];  // fp16 copies of q,k,v
__device__ __half g_at_hi[(size_t)NROWS * DDIM];
__device__ __half g_wt_hi[4 * DDIM * DDIM];          // transposed: Wt[n][k]
__device__ __half g_fh[(size_t)NROWS * DDIM];        // fh in fp16

// ---------------------------------------------------------------------------
// helpers
// ---------------------------------------------------------------------------
__device__ __forceinline__ uint32_t s2u(const void* p) {
    uint32_t a;
    asm("{ .reg .u64 t; cvta.to.shared.u64 t, %1; cvt.u32.u64 %0, t; }"
        : "=r"(a) : "l"(p));
    return a;
}

__device__ __forceinline__ void cpasync16(uint32_t dst, const void* src) {
    asm volatile("cp.async.cg.shared.global [%0], [%1], 16;" :: "r"(dst), "l"(src));
}
__device__ __forceinline__ void cp_commit() {
    asm volatile("cp.async.commit_group;" ::: "memory");
}
__device__ __forceinline__ void cp_wait1() {
    asm volatile("cp.async.wait_group 1;" ::: "memory");
}

__device__ __forceinline__ void ldm_x4(uint32_t* r, uint32_t addr) {
    asm volatile("ldmatrix.sync.aligned.m8n8.x4.shared.b16 {%0,%1,%2,%3}, [%4];"
                 : "=r"(r[0]), "=r"(r[1]), "=r"(r[2]), "=r"(r[3]) : "r"(addr));
}

__device__ __forceinline__ void mma16816(float* c, const uint32_t* a, const uint32_t* b) {
    asm volatile(
        "mma.sync.aligned.m16n8k16.row.col.f32.f16.f16.f32 "
        "{%0,%1,%2,%3}, {%4,%5,%6,%7}, {%8,%9}, {%0,%1,%2,%3};"
        : "+f"(c[0]), "+f"(c[1]), "+f"(c[2]), "+f"(c[3])
        : "r"(a[0]), "r"(a[1]), "r"(a[2]), "r"(a[3]), "r"(b[0]), "r"(b[1]));
}

// SW128 swizzle for 128B rows (64 halves): seg(0..7) XOR low row bits
__device__ __forceinline__ uint32_t swz128(int row, int seg) {
    return (uint32_t)(row * 128 + ((seg ^ (row & 7)) << 4));
}

// ---------------------------------------------------------------------------
// Conversion: h fp32 -> fp16
// ---------------------------------------------------------------------------
__global__ __launch_bounds__(256) void conv_h(const float* __restrict__ src,
                                              __half* __restrict__ hi) {
    const size_t i4 = (size_t)blockIdx.x * 256 + threadIdx.x;
    float4 x = ((const float4*)src)[i4];
    __half2 h01, h23;
    h01.x = __float2half(x.x); h01.y = __float2half(x.y);
    h23.x = __float2half(x.z); h23.y = __float2half(x.w);
    ((__half2*)hi)[i4 * 2]     = h01;
    ((__half2*)hi)[i4 * 2 + 1] = h23;
}

// ---------------------------------------------------------------------------
// Conversion + transpose: W[k][n] fp32 -> Wt[n][k] fp16 (4 matrices)
// ---------------------------------------------------------------------------
__global__ __launch_bounds__(256) void conv_wt(const float* __restrict__ W0,
                                               const float* __restrict__ W1,
                                               const float* __restrict__ W2,
                                               const float* __restrict__ W3,
                                               __half* __restrict__ hi) {
    const float* W = (blockIdx.z == 0) ? W0 : (blockIdx.z == 1) ? W1
                     : (blockIdx.z == 2) ? W2 : W3;
    __shared__ float t[32][33];
    const int tx = threadIdx.x, ty = threadIdx.y;  // 32 x 8
    const int n0 = blockIdx.x * 32, k0 = blockIdx.y * 32;
#pragma unroll
    for (int i = 0; i < 4; ++i)
        t[ty + i * 8][tx] = W[(size_t)(k0 + ty + i * 8) * DDIM + n0 + tx];
    __syncthreads();
    const size_t base = (size_t)blockIdx.z * DDIM * DDIM;
#pragma unroll
    for (int i = 0; i < 4; ++i) {
        const int n = n0 + ty + i * 8;
        const int k = k0 + tx;
        hi[base + (size_t)n * DDIM + k] = __float2half(t[tx][ty + i * 8]);
    }
}

// ---------------------------------------------------------------------------
// HMMA fp16 GEMM: C = A @ Wt^T, fp32 accum, direct-store epilogue.
// CTA 128x128, BK=64, 8 warps (64x32), 3-stage cp.async, SW128 + ldmatrix.
// QKV=true: gridDim.z selects weight/output slab; relu for z<2; fp32 C to
// out slabs + fp16 copy to Ch. QKV=false: fp16 C only (fh).
// ---------------------------------------------------------------------------
#define TILE_B   (128 * 128)             // 16384 B per operand tile (BK=64)
#define NSTAGE   3
#define STAGE_B  (2 * TILE_B)            // Ah, Bh = 32768 B
#define SMEM_DYN (NSTAGE * STAGE_B)      // 98304 B -> 2 CTAs/SM

template <bool QKV>
__global__ __launch_bounds__(256) void gemm_mma(const __half* __restrict__ Ah,
                                                const __half* __restrict__ Bh0,
                                                float* __restrict__ C0,
                                                __half* __restrict__ Ch0) {
    extern __shared__ char dsm[];
    const uint32_t sb = s2u(dsm);

    const int tid  = threadIdx.x;
    const int wid  = tid >> 5;
    const int lane = tid & 31;
    const int bm   = blockIdx.y * 128;
    const int bn   = blockIdx.x * 128;

    const size_t zoffW = QKV ? (size_t)blockIdx.z * DDIM * DDIM : 0;
    const size_t zoffC = QKV ? (size_t)blockIdx.z * NROWS * DDIM : 0;
    const __half* Bh = Bh0 + zoffW;
    float* C = QKV ? (C0 + zoffC) : nullptr;
    __half* Ch = Ch0 + zoffC;
    const bool relu = QKV ? (blockIdx.z < 2) : false;

    const int wm = (wid & 1) * 64;   // warp m offset
    const int wn = (wid >> 1) * 32;  // warp n offset

    float acc[4][4][4];
#pragma unroll
    for (int i = 0; i < 4; ++i)
#pragma unroll
        for (int j = 0; j < 4; ++j)
#pragma unroll
            for (int r = 0; r < 4; ++r) acc[i][j][r] = 0.0f;

    // stage loader: 2 tiles x 128 rows x 8 segs = 2048 chunks, 8 per thread
    auto load_stage = [&](int stage, int kc) {
        const uint32_t s0 = sb + stage * STAGE_B;
#pragma unroll
        for (int it = 0; it < 4; ++it) {
            const int ch  = tid + it * 256;     // 0..1023
            const int row = ch >> 3;
            const int seg = ch & 7;
            cpasync16(s0 + swz128(row, seg),
                      Ah + (size_t)(bm + row) * DDIM + kc + seg * 8);
            cpasync16(s0 + TILE_B + swz128(row, seg),
                      Bh + (size_t)(bn + row) * DDIM + kc + seg * 8);
        }
    };

    // prologue: stages 0,1
    load_stage(0, 0);
    cp_commit();
    load_stage(1, 64);
    cp_commit();

    // ldmatrix lane roles
    const int a_row = lane & 15;
    const int a_sg  = lane >> 4;                 // 16B within k16 (0/1)
    const int b_row = ((lane >> 4) & 1) * 8 + (lane & 7);
    const int b_sg  = (lane >> 3) & 1;

    for (int kt = 0; kt < 8; ++kt) {
        cp_wait1();          // stage kt resident
        __syncthreads();     // stage (kt+2)%3 free

        if (kt + 2 < 8) load_stage((kt + 2) % NSTAGE, (kt + 2) * 64);
        cp_commit();

        const uint32_t s0  = sb + (kt % NSTAGE) * STAGE_B;
        const uint32_t aho = s0;
        const uint32_t bho = s0 + TILE_B;

#pragma unroll
        for (int s = 0; s < 4; ++s) {
            const int ksg = s * 2;               // 16B-seg base of this k16
            uint32_t bh[4][2];
#pragma unroll
            for (int jp = 0; jp < 2; ++jp) {
                const uint32_t ba = swz128(wn + jp * 16 + b_row, ksg + b_sg);
                uint32_t r[4];
                ldm_x4(r, bho + ba);
                bh[jp * 2][0] = r[0]; bh[jp * 2][1] = r[1];
                bh[jp * 2 + 1][0] = r[2]; bh[jp * 2 + 1][1] = r[3];
            }
#pragma unroll
            for (int i = 0; i < 4; ++i) {
                const uint32_t aa = swz128(wm + i * 16 + a_row, ksg + a_sg);
                uint32_t ah[4];
                ldm_x4(ah, aho + aa);
#pragma unroll
                for (int j = 0; j < 4; ++j) mma16816(acc[i][j], ah, bh[j]);
            }
        }
    }

    // direct-store epilogue: each (i,j) fragment writes two 8B float2 runs
    // (32B-contiguous across lanes 0-3 per row = one DRAM sector).
    const int r4 = lane >> 2;
    const int c2 = (lane & 3) * 2;
#pragma unroll
    for (int i = 0; i < 4; ++i) {
        const int row0 = bm + wm + i * 16 + r4;
#pragma unroll
        for (int j = 0; j < 4; ++j) {
            const int col = bn + wn + j * 8 + c2;
            float d0 = acc[i][j][0], d1 = acc[i][j][1];
            float d2 = acc[i][j][2], d3 = acc[i][j][3];
            if (relu) {
                d0 = fmaxf(d0, 0.0f); d1 = fmaxf(d1, 0.0f);
                d2 = fmaxf(d2, 0.0f); d3 = fmaxf(d3, 0.0f);
            }
            if (QKV) {
                *(float2*)(C + (size_t)row0 * DDIM + col)       = make_float2(d0, d1);
                *(float2*)(C + (size_t)(row0 + 8) * DDIM + col) = make_float2(d2, d3);
            }
            __half2 p0, p1;
            p0.x = __float2half(d0); p0.y = __float2half(d1);
            p1.x = __float2half(d2); p1.y = __float2half(d3);
            *(__half2*)(Ch + (size_t)row0 * DDIM + col)       = p0;
            *(__half2*)(Ch + (size_t)(row0 + 8) * DDIM + col) = p1;
        }
    }
}

// ---------------------------------------------------------------------------
// Per-node linear attention via 8x8 score matrix, fp16 inputs.
// ---------------------------------------------------------------------------
#define PADH 72   // halves per head row for q,k
#define PADR 68   // floats per head row for v

__global__ __launch_bounds__(256) void attn2(const __half* __restrict__ q,
                                             const __half* __restrict__ k,
                                             const __half* __restrict__ v,
                                             __half* __restrict__ ahi) {
    __shared__ __half hq[4][NHEADS * PADH];
    __shared__ __half hk[4][NHEADS * PADH];
    __shared__ float  sv[4][NHEADS * PADR];
    __shared__ float  Ss[4][NHEADS * NHEADS];

    const int tid = threadIdx.x;
    const int ln  = tid >> 6;
    const int t   = tid & 63;
    const size_t base = ((size_t)blockIdx.x * 4 + ln) * DDIM;

    {
        const int i8 = t * 8;           // 0..504
        const int h  = i8 >> 6;
        const int d  = i8 & 63;
        *(uint4*)&hq[ln][h * PADH + d] = *(const uint4*)(q + base + i8);
        *(uint4*)&hk[ln][h * PADH + d] = *(const uint4*)(k + base + i8);
        const __half2* vp = (const __half2*)(v + base + i8);
#pragma unroll
        for (int j = 0; j < 4; ++j) {
            float2 fv = __half22float2(vp[j]);
            sv[ln][h * PADR + d + 2 * j]     = fv.x;
            sv[ln][h * PADR + d + 2 * j + 1] = fv.y;
        }
    }
    __syncthreads();

    {
        const uint4* qp = (const uint4*)&hq[ln][(t >> 3) * PADH];
        const uint4* kp = (const uint4*)&hk[ln][(t & 7) * PADH];
        float s = 0.0f;
#pragma unroll
        for (int c = 0; c < 8; ++c) {
            uint4 a = qp[c], b = kp[c];
            const __half2* ah = (const __half2*)&a;
            const __half2* bh = (const __half2*)&b;
#pragma unroll
            for (int j = 0; j < 4; ++j) {
                float2 fa = __half22float2(ah[j]);
                float2 fb = __half22float2(bh[j]);
                s = fmaf(fa.x, fb.x, s);
                s = fmaf(fa.y, fb.y, s);
            }
        }
        Ss[ln][t] = s;
    }
    __syncthreads();

    {
        const int e = t;
        float sval[NHEADS];
#pragma unroll
        for (int hp = 0; hp < NHEADS; ++hp) sval[hp] = sv[ln][hp * PADR + e];
#pragma unroll
        for (int h = 0; h < NHEADS; ++h) {
            float num = 0.0f, den = 0.0f;
#pragma unroll
            for (int hp = 0; hp < NHEADS; ++hp) {
                const float Sv = Ss[ln][h * NHEADS + hp];
                den += Sv;
                num = fmaf(Sv, sval[hp], num);
            }
            ahi[base + h * HDIM + e] = __float2half(__fdividef(num, den));
        }
    }
}

// ---------------------------------------------------------------------------
// Fused residual + LayerNorm, one warp per row. fh read as fp16.
// ---------------------------------------------------------------------------
__global__ __launch_bounds__(256) void ln_kernel(const float* __restrict__ h,
                                                 const __half* __restrict__ fh,
                                                 const float* __restrict__ gamma,
                                                 const float* __restrict__ beta,
                                                 float* __restrict__ out) {
    const int row  = (blockIdx.x * blockDim.x + threadIdx.x) >> 5;
    const int lane = threadIdx.x & 31;
    if (row >= NROWS) return;

    const size_t b4 = (size_t)row * 128;   // float4 base
    const size_t b8h = (size_t)row * 256;  // half2 base
    float4 x[4];
    float s = 0.0f;
#pragma unroll
    for (int i = 0; i < 4; ++i) {
        const int c = lane + i * 32;
        float4 a = ((const float4*)h)[b4 + c];
        const __half2* fp = ((const __half2*)fh) + b8h + c * 2;
        float2 f0 = __half22float2(fp[0]);
        float2 f1 = __half22float2(fp[1]);
        x[i].x = a.x + f0.x; x[i].y = a.y + f0.y;
        x[i].z = a.z + f1.x; x[i].w = a.w + f1.y;
        s += x[i].x + x[i].y + x[i].z + x[i].w;
    }
#pragma unroll
    for (int off = 16; off > 0; off >>= 1) s += __shfl_xor_sync(0xffffffffu, s, off);
    const float mu = s * (1.0f / DDIM);

    float var = 0.0f;
#pragma unroll
    for (int i = 0; i < 4; ++i) {
        float dx = x[i].x - mu, dy = x[i].y - mu, dz = x[i].z - mu, dw = x[i].w - mu;
        var = fmaf(dx, dx, var); var = fmaf(dy, dy, var);
        var = fmaf(dz, dz, var); var = fmaf(dw, dw, var);
    }
#pragma unroll
    for (int off = 16; off > 0; off >>= 1) var += __shfl_xor_sync(0xffffffffu, var, off);
    var *= (1.0f / DDIM);

    const float r = rsqrtf(var + LN_EPS);
#pragma unroll
    for (int i = 0; i < 4; ++i) {
        const int c = lane + i * 32;
        float4 g = ((const float4*)gamma)[c];
        float4 bt = ((const float4*)beta)[c];
        float4 o;
        o.x = (x[i].x - mu) * r * g.x + bt.x;
        o.y = (x[i].y - mu) * r * g.y + bt.y;
        o.z = (x[i].z - mu) * r * g.z + bt.z;
        o.w = (x[i].w - mu) * r * g.w + bt.w;
        ((float4*)out)[b4 + c] = o;
    }
}

// ---------------------------------------------------------------------------
// kernel_launch
// ---------------------------------------------------------------------------
extern "C" void kernel_launch(void* const* d_in, const int* in_sizes, int n_in,
                              void* d_out, int out_size) {
    const float* h     = (const float*)d_in[0];
    const float* Wq    = (const float*)d_in[1];
    const float* Wk    = (const float*)d_in[2];
    const float* Wv    = (const float*)d_in[3];
    const float* Wf    = (const float*)d_in[4];
    const float* gamma = (const float*)d_in[5];
    const float* beta  = (const float*)d_in[6];

    float* out = (float*)d_out;
    float* q   = out + (size_t)NROWS * DDIM;

    void *hhi, *qkvh, *athi, *wthi, *fhp;
    cudaGetSymbolAddress(&hhi, g_h_hi);
    cudaGetSymbolAddress(&qkvh, g_qkvh);
    cudaGetSymbolAddress(&athi, g_at_hi);
    cudaGetSymbolAddress(&wthi, g_wt_hi);
    cudaGetSymbolAddress(&fhp, g_fh);

    cudaFuncSetAttribute(gemm_mma<true>,
                         cudaFuncAttributeMaxDynamicSharedMemorySize, SMEM_DYN);
    cudaFuncSetAttribute(gemm_mma<false>,
                         cudaFuncAttributeMaxDynamicSharedMemorySize, SMEM_DYN);

    __half* Hhi  = (__half*)hhi;
    __half* Qkvh = (__half*)qkvh;
    __half* Ath  = (__half*)athi;
    __half* WTh  = (__half*)wthi;
    __half* Fh   = (__half*)fhp;

    conv_h<<<(NROWS * DDIM) / 4 / 256, 256>>>(h, Hhi);
    conv_wt<<<dim3(16, 16, 4), dim3(32, 8)>>>(Wq, Wk, Wv, Wf, WTh);

    const size_t WSZ = (size_t)DDIM * DDIM;
    const size_t NDS = (size_t)NROWS * DDIM;

    // fused q,k,v projections (z = 0,1,2); fp32 to out slabs + fp16 to Qkvh
    gemm_mma<true><<<dim3(4, 256, 3), 256, SMEM_DYN>>>(Hhi, WTh, q, Qkvh);

    attn2<<<NROWS / 4, 256>>>(Qkvh, Qkvh + NDS, Qkvh + 2 * NDS, Ath);

    // Wf GEMM: fp16 x fp16 -> fp16 fh
    gemm_mma<false><<<dim3(4, 256, 1), 256, SMEM_DYN>>>(
        Ath, WTh + 3 * WSZ, nullptr, Fh);

    ln_kernel<<<(NROWS * 32) / 256, 256>>>(h, Fh, gamma, beta, out);
}

// round 15
// speedup vs baseline: 2.5797x; 1.0101x over previous
#include <cuda_runtime.h>
#include <cuda_fp16.h>
#include <cstdint>

// Problem constants (AGTLayer: N=32768, D=512, H=8, HD=64)
#define NROWS 32768
#define DDIM  512
#define NHEADS 8
#define HDIM  64
#define LN_EPS 1e-5f

// ---------------------------------------------------------------------------
// Scratch (__device__ globals; allocation-free rule)
// ---------------------------------------------------------------------------
__device__ __half g_h_hi[(size_t)NROWS * DDIM];
__device__ __half g_qkvh[3 * (size_t)NROWS * DDIM];  // fp16 copies of q,k,v
__device__ __half g_at_hi[(size_t)NROWS * DDIM];
__device__ __half g_wt_hi[4 * DDIM * DDIM];          // transposed: Wt[n][k]
__device__ __half g_fh[(size_t)NROWS * DDIM];        // fh in fp16

// ---------------------------------------------------------------------------
// helpers
// ---------------------------------------------------------------------------
__device__ __forceinline__ uint32_t s2u(const void* p) {
    uint32_t a;
    asm("{ .reg .u64 t; cvta.to.shared.u64 t, %1; cvt.u32.u64 %0, t; }"
        : "=r"(a) : "l"(p));
    return a;
}

__device__ __forceinline__ void cpasync16(uint32_t dst, const void* src) {
    asm volatile("cp.async.cg.shared.global [%0], [%1], 16;" :: "r"(dst), "l"(src));
}
__device__ __forceinline__ void cp_commit() {
    asm volatile("cp.async.commit_group;" ::: "memory");
}
__device__ __forceinline__ void cp_wait1() {
    asm volatile("cp.async.wait_group 1;" ::: "memory");
}

__device__ __forceinline__ void ldm_x4(uint32_t* r, uint32_t addr) {
    asm volatile("ldmatrix.sync.aligned.m8n8.x4.shared.b16 {%0,%1,%2,%3}, [%4];"
                 : "=r"(r[0]), "=r"(r[1]), "=r"(r[2]), "=r"(r[3]) : "r"(addr));
}

__device__ __forceinline__ void mma16816(float* c, const uint32_t* a, const uint32_t* b) {
    asm volatile(
        "mma.sync.aligned.m16n8k16.row.col.f32.f16.f16.f32 "
        "{%0,%1,%2,%3}, {%4,%5,%6,%7}, {%8,%9}, {%0,%1,%2,%3};"
        : "+f"(c[0]), "+f"(c[1]), "+f"(c[2]), "+f"(c[3])
        : "r"(a[0]), "r"(a[1]), "r"(a[2]), "r"(a[3]), "r"(b[0]), "r"(b[1]));
}

// SW128 swizzle for 128B rows (64 halves): seg(0..7) XOR low row bits
__device__ __forceinline__ uint32_t swz128(int row, int seg) {
    return (uint32_t)(row * 128 + ((seg ^ (row & 7)) << 4));
}

// packed f32x2 helpers
__device__ __forceinline__ unsigned long long packf2(float lo, float hi) {
    unsigned long long p;
    asm("mov.b64 %0, {%1, %2};" : "=l"(p) : "f"(lo), "f"(hi));
    return p;
}
__device__ __forceinline__ void fma2(unsigned long long& acc, unsigned long long a,
                                     unsigned long long b) {
    asm("fma.rn.f32x2 %0, %1, %2, %0;" : "+l"(acc) : "l"(a), "l"(b));
}

// ---------------------------------------------------------------------------
// Fused conversions: blocks [0,1024): W transpose (4 matrices); rest: h->fp16
// ---------------------------------------------------------------------------
__global__ __launch_bounds__(256) void conv_all(const float* __restrict__ h,
                                                const float* __restrict__ W0,
                                                const float* __restrict__ W1,
                                                const float* __restrict__ W2,
                                                const float* __restrict__ W3,
                                                __half* __restrict__ hhi,
                                                __half* __restrict__ whi) {
    const int bx = blockIdx.x;
    if (bx < 1024) {
        const int z   = bx >> 8;
        const int rem = bx & 255;
        const float* W = (z == 0) ? W0 : (z == 1) ? W1 : (z == 2) ? W2 : W3;
        __shared__ float t[32][33];
        const int tx = threadIdx.x & 31, ty = threadIdx.x >> 5;  // 32 x 8
        const int n0 = (rem & 15) * 32, k0 = (rem >> 4) * 32;
#pragma unroll
        for (int i = 0; i < 4; ++i)
            t[ty + i * 8][tx] = W[(size_t)(k0 + ty + i * 8) * DDIM + n0 + tx];
        __syncthreads();
        const size_t base = (size_t)z * DDIM * DDIM;
#pragma unroll
        for (int i = 0; i < 4; ++i) {
            const int n = n0 + ty + i * 8;
            const int k = k0 + tx;
            whi[base + (size_t)n * DDIM + k] = __float2half(t[tx][ty + i * 8]);
        }
    } else {
        const size_t i4 = (size_t)(bx - 1024) * 256 + threadIdx.x;
        float4 x = ((const float4*)h)[i4];
        __half2 h01, h23;
        h01.x = __float2half(x.x); h01.y = __float2half(x.y);
        h23.x = __float2half(x.z); h23.y = __float2half(x.w);
        ((__half2*)hhi)[i4 * 2]     = h01;
        ((__half2*)hhi)[i4 * 2 + 1] = h23;
    }
}

// ---------------------------------------------------------------------------
// HMMA fp16 GEMM: C = A @ Wt^T, fp32 accum, direct-store epilogue.
// CTA 128x128, BK=64, 8 warps (64x32), 3-stage cp.async, SW128 + ldmatrix.
// ---------------------------------------------------------------------------
#define TILE_B   (128 * 128)             // 16384 B per operand tile (BK=64)
#define NSTAGE   3
#define STAGE_B  (2 * TILE_B)            // Ah, Bh = 32768 B
#define SMEM_DYN (NSTAGE * STAGE_B)      // 98304 B -> 2 CTAs/SM

template <bool QKV>
__global__ __launch_bounds__(256) void gemm_mma(const __half* __restrict__ Ah,
                                                const __half* __restrict__ Bh0,
                                                float* __restrict__ C0,
                                                __half* __restrict__ Ch0) {
    extern __shared__ char dsm[];
    const uint32_t sb = s2u(dsm);

    const int tid  = threadIdx.x;
    const int wid  = tid >> 5;
    const int lane = tid & 31;
    const int bm   = blockIdx.y * 128;
    const int bn   = blockIdx.x * 128;

    const size_t zoffW = QKV ? (size_t)blockIdx.z * DDIM * DDIM : 0;
    const size_t zoffC = QKV ? (size_t)blockIdx.z * NROWS * DDIM : 0;
    const __half* Bh = Bh0 + zoffW;
    float* C = QKV ? (C0 + zoffC) : nullptr;
    __half* Ch = Ch0 + zoffC;
    const bool relu = QKV ? (blockIdx.z < 2) : false;

    const int wm = (wid & 1) * 64;   // warp m offset
    const int wn = (wid >> 1) * 32;  // warp n offset

    float acc[4][4][4];
#pragma unroll
    for (int i = 0; i < 4; ++i)
#pragma unroll
        for (int j = 0; j < 4; ++j)
#pragma unroll
            for (int r = 0; r < 4; ++r) acc[i][j][r] = 0.0f;

    auto load_stage = [&](int stage, int kc) {
        const uint32_t s0 = sb + stage * STAGE_B;
#pragma unroll
        for (int it = 0; it < 4; ++it) {
            const int ch  = tid + it * 256;     // 0..1023
            const int row = ch >> 3;
            const int seg = ch & 7;
            cpasync16(s0 + swz128(row, seg),
                      Ah + (size_t)(bm + row) * DDIM + kc + seg * 8);
            cpasync16(s0 + TILE_B + swz128(row, seg),
                      Bh + (size_t)(bn + row) * DDIM + kc + seg * 8);
        }
    };

    load_stage(0, 0);
    cp_commit();
    load_stage(1, 64);
    cp_commit();

    const int a_row = lane & 15;
    const int a_sg  = lane >> 4;
    const int b_row = ((lane >> 4) & 1) * 8 + (lane & 7);
    const int b_sg  = (lane >> 3) & 1;

    for (int kt = 0; kt < 8; ++kt) {
        cp_wait1();
        __syncthreads();

        if (kt + 2 < 8) load_stage((kt + 2) % NSTAGE, (kt + 2) * 64);
        cp_commit();

        const uint32_t s0  = sb + (kt % NSTAGE) * STAGE_B;
        const uint32_t aho = s0;
        const uint32_t bho = s0 + TILE_B;

#pragma unroll
        for (int s = 0; s < 4; ++s) {
            const int ksg = s * 2;
            uint32_t bh[4][2];
#pragma unroll
            for (int jp = 0; jp < 2; ++jp) {
                const uint32_t ba = swz128(wn + jp * 16 + b_row, ksg + b_sg);
                uint32_t r[4];
                ldm_x4(r, bho + ba);
                bh[jp * 2][0] = r[0]; bh[jp * 2][1] = r[1];
                bh[jp * 2 + 1][0] = r[2]; bh[jp * 2 + 1][1] = r[3];
            }
#pragma unroll
            for (int i = 0; i < 4; ++i) {
                const uint32_t aa = swz128(wm + i * 16 + a_row, ksg + a_sg);
                uint32_t ah[4];
                ldm_x4(ah, aho + aa);
#pragma unroll
                for (int j = 0; j < 4; ++j) mma16816(acc[i][j], ah, bh[j]);
            }
        }
    }

    // direct-store epilogue
    const int r4 = lane >> 2;
    const int c2 = (lane & 3) * 2;
#pragma unroll
    for (int i = 0; i < 4; ++i) {
        const int row0 = bm + wm + i * 16 + r4;
#pragma unroll
        for (int j = 0; j < 4; ++j) {
            const int col = bn + wn + j * 8 + c2;
            float d0 = acc[i][j][0], d1 = acc[i][j][1];
            float d2 = acc[i][j][2], d3 = acc[i][j][3];
            if (relu) {
                d0 = fmaxf(d0, 0.0f); d1 = fmaxf(d1, 0.0f);
                d2 = fmaxf(d2, 0.0f); d3 = fmaxf(d3, 0.0f);
            }
            if (QKV) {
                *(float2*)(C + (size_t)row0 * DDIM + col)       = make_float2(d0, d1);
                *(float2*)(C + (size_t)(row0 + 8) * DDIM + col) = make_float2(d2, d3);
            }
            __half2 p0, p1;
            p0.x = __float2half(d0); p0.y = __float2half(d1);
            p1.x = __float2half(d2); p1.y = __float2half(d3);
            *(__half2*)(Ch + (size_t)row0 * DDIM + col)       = p0;
            *(__half2*)(Ch + (size_t)(row0 + 8) * DDIM + col) = p1;
        }
    }
}

// ---------------------------------------------------------------------------
// Per-node linear attention via 8x8 score matrix, fp16 inputs.
// q,k,v in fp16 smem; dot phase uses packed fma.rn.f32x2 (fp32 precision).
// 4 nodes/block, 64 threads/node.
// ---------------------------------------------------------------------------
#define PADH 72   // halves per head row (144 B)

__global__ __launch_bounds__(256) void attn2(const __half* __restrict__ q,
                                             const __half* __restrict__ k,
                                             const __half* __restrict__ v,
                                             __half* __restrict__ ahi) {
    __shared__ __half hq[4][NHEADS * PADH];
    __shared__ __half hk[4][NHEADS * PADH];
    __shared__ __half hv[4][NHEADS * PADH];
    __shared__ float  Ss[4][NHEADS * NHEADS];

    const int tid = threadIdx.x;
    const int ln  = tid >> 6;
    const int t   = tid & 63;
    const size_t base = ((size_t)blockIdx.x * 4 + ln) * DDIM;

    {
        const int i8 = t * 8;           // 0..504
        const int h  = i8 >> 6;
        const int d  = i8 & 63;
        *(uint4*)&hq[ln][h * PADH + d] = *(const uint4*)(q + base + i8);
        *(uint4*)&hk[ln][h * PADH + d] = *(const uint4*)(k + base + i8);
        *(uint4*)&hv[ln][h * PADH + d] = *(const uint4*)(v + base + i8);
    }
    __syncthreads();

    // dot: thread t computes S[t>>3][t&7] with packed f32x2 FMA
    {
        const uint4* qp = (const uint4*)&hq[ln][(t >> 3) * PADH];
        const uint4* kp = (const uint4*)&hk[ln][(t & 7) * PADH];
        unsigned long long acc2 = 0ull;   // packed {0.0f, 0.0f}
#pragma unroll
        for (int c = 0; c < 8; ++c) {
            uint4 a = qp[c], b = kp[c];
            const __half2* ah = (const __half2*)&a;
            const __half2* bh = (const __half2*)&b;
#pragma unroll
            for (int j = 0; j < 4; ++j) {
                float2 fa = __half22float2(ah[j]);
                float2 fb = __half22float2(bh[j]);
                fma2(acc2, packf2(fa.x, fa.y), packf2(fb.x, fb.y));
            }
        }
        float lo, hi;
        asm("mov.b64 {%0, %1}, %2;" : "=f"(lo), "=f"(hi) : "l"(acc2));
        Ss[ln][t] = lo + hi;
    }
    __syncthreads();

    // output: thread t owns column e=t for all 8 heads
    {
        const int e = t;
        float sval[NHEADS];
#pragma unroll
        for (int hp = 0; hp < NHEADS; ++hp)
            sval[hp] = __half2float(hv[ln][hp * PADH + e]);
#pragma unroll
        for (int h = 0; h < NHEADS; ++h) {
            float num = 0.0f, den = 0.0f;
#pragma unroll
            for (int hp = 0; hp < NHEADS; ++hp) {
                const float Sv = Ss[ln][h * NHEADS + hp];
                den += Sv;
                num = fmaf(Sv, sval[hp], num);
            }
            ahi[base + h * HDIM + e] = __float2half(__fdividef(num, den));
        }
    }
}

// ---------------------------------------------------------------------------
// Fused residual + LayerNorm, one warp per row. fh read as fp16.
// ---------------------------------------------------------------------------
__global__ __launch_bounds__(256) void ln_kernel(const float* __restrict__ h,
                                                 const __half* __restrict__ fh,
                                                 const float* __restrict__ gamma,
                                                 const float* __restrict__ beta,
                                                 float* __restrict__ out) {
    const int row  = (blockIdx.x * blockDim.x + threadIdx.x) >> 5;
    const int lane = threadIdx.x & 31;
    if (row >= NROWS) return;

    const size_t b4 = (size_t)row * 128;   // float4 base
    const size_t b8h = (size_t)row * 256;  // half2 base
    float4 x[4];
    float s = 0.0f;
#pragma unroll
    for (int i = 0; i < 4; ++i) {
        const int c = lane + i * 32;
        float4 a = ((const float4*)h)[b4 + c];
        const __half2* fp = ((const __half2*)fh) + b8h + c * 2;
        float2 f0 = __half22float2(fp[0]);
        float2 f1 = __half22float2(fp[1]);
        x[i].x = a.x + f0.x; x[i].y = a.y + f0.y;
        x[i].z = a.z + f1.x; x[i].w = a.w + f1.y;
        s += x[i].x + x[i].y + x[i].z + x[i].w;
    }
#pragma unroll
    for (int off = 16; off > 0; off >>= 1) s += __shfl_xor_sync(0xffffffffu, s, off);
    const float mu = s * (1.0f / DDIM);

    float var = 0.0f;
#pragma unroll
    for (int i = 0; i < 4; ++i) {
        float dx = x[i].x - mu, dy = x[i].y - mu, dz = x[i].z - mu, dw = x[i].w - mu;
        var = fmaf(dx, dx, var); var = fmaf(dy, dy, var);
        var = fmaf(dz, dz, var); var = fmaf(dw, dw, var);
    }
#pragma unroll
    for (int off = 16; off > 0; off >>= 1) var += __shfl_xor_sync(0xffffffffu, var, off);
    var *= (1.0f / DDIM);

    const float r = rsqrtf(var + LN_EPS);
#pragma unroll
    for (int i = 0; i < 4; ++i) {
        const int c = lane + i * 32;
        float4 g = ((const float4*)gamma)[c];
        float4 bt = ((const float4*)beta)[c];
        float4 o;
        o.x = (x[i].x - mu) * r * g.x + bt.x;
        o.y = (x[i].y - mu) * r * g.y + bt.y;
        o.z = (x[i].z - mu) * r * g.z + bt.z;
        o.w = (x[i].w - mu) * r * g.w + bt.w;
        ((float4*)out)[b4 + c] = o;
    }
}

// ---------------------------------------------------------------------------
// kernel_launch
// ---------------------------------------------------------------------------
extern "C" void kernel_launch(void* const* d_in, const int* in_sizes, int n_in,
                              void* d_out, int out_size) {
    const float* h     = (const float*)d_in[0];
    const float* Wq    = (const float*)d_in[1];
    const float* Wk    = (const float*)d_in[2];
    const float* Wv    = (const float*)d_in[3];
    const float* Wf    = (const float*)d_in[4];
    const float* gamma = (const float*)d_in[5];
    const float* beta  = (const float*)d_in[6];

    float* out = (float*)d_out;
    float* q   = out + (size_t)NROWS * DDIM;

    void *hhi, *qkvh, *athi, *wthi, *fhp;
    cudaGetSymbolAddress(&hhi, g_h_hi);
    cudaGetSymbolAddress(&qkvh, g_qkvh);
    cudaGetSymbolAddress(&athi, g_at_hi);
    cudaGetSymbolAddress(&wthi, g_wt_hi);
    cudaGetSymbolAddress(&fhp, g_fh);

    cudaFuncSetAttribute(gemm_mma<true>,
                         cudaFuncAttributeMaxDynamicSharedMemorySize, SMEM_DYN);
    cudaFuncSetAttribute(gemm_mma<false>,
                         cudaFuncAttributeMaxDynamicSharedMemorySize, SMEM_DYN);

    __half* Hhi  = (__half*)hhi;
    __half* Qkvh = (__half*)qkvh;
    __half* Ath  = (__half*)athi;
    __half* WTh  = (__half*)wthi;
    __half* Fh   = (__half*)fhp;

    // fused conversions: 1024 W-transpose blocks + 16384 h-conversion blocks
    conv_all<<<1024 + (NROWS * DDIM) / 4 / 256, 256>>>(h, Wq, Wk, Wv, Wf, Hhi, WTh);

    const size_t WSZ = (size_t)DDIM * DDIM;
    const size_t NDS = (size_t)NROWS * DDIM;

    // fused q,k,v projections (z = 0,1,2); fp32 to out slabs + fp16 to Qkvh
    gemm_mma<true><<<dim3(4, 256, 3), 256, SMEM_DYN>>>(Hhi, WTh, q, Qkvh);

    attn2<<<NROWS / 4, 256>>>(Qkvh, Qkvh + NDS, Qkvh + 2 * NDS, Ath);

    // Wf GEMM: fp16 x fp16 -> fp16 fh
    gemm_mma<false><<<dim3(4, 256, 1), 256, SMEM_DYN>>>(
        Ath, WTh + 3 * WSZ, nullptr, Fh);

    ln_kernel<<<(NROWS * 32) / 256, 256>>>(h, Fh, gamma, beta, out);
}